// round 12
// baseline (speedup 1.0000x reference)
#include <cuda_runtime.h>
#include <math.h>

#define NN 6144
#define NDRUG 3072

// ---------- scratch (device globals; no allocation allowed) ----------
__device__ __align__(16) float g_norm[NN];
__device__ __align__(16) float g_xn[NN * 64];
__device__ __align__(16) float g_target[NN * 64];
__device__ __align__(16) float g_aux[NN * 64];
__device__ __align__(16) float g_q[4 * NN * 16];    // head-major
__device__ __align__(16) float g_k[4 * NN * 16];
__device__ __align__(16) float g_v[4 * NN * 16];
__device__ __align__(16) float g_oacc[NN * 64];
__device__ __align__(16) float g_lacc[NN * 4];

#define MMA_TF32(D, A, B0, B1) \
    asm volatile("mma.sync.aligned.m16n8k8.row.col.f32.tf32.tf32.f32 " \
                 "{%0,%1,%2,%3},{%4,%5,%6,%7},{%8,%9},{%0,%1,%2,%3};" \
                 : "+f"((D)[0]), "+f"((D)[1]), "+f"((D)[2]), "+f"((D)[3]) \
                 : "r"((A)[0]), "r"((A)[1]), "r"((A)[2]), "r"((A)[3]), "r"(B0), "r"(B1))

// ===== K1: degree norms + per-type projection + zero accumulators. grid 768, block 256 =====
__global__ __launch_bounds__(256) void k_degproj(const float* __restrict__ graph,
                                                 const float* __restrict__ drug_f,
                                                 const float* __restrict__ dis_f,
                                                 const float* __restrict__ drug_w,
                                                 const float* __restrict__ dis_w) {
    __shared__ float w[4096];
    __shared__ float fr[512];
    __shared__ float nrm[8];
    int tid = threadIdx.x;
    int wid = tid >> 5, lane = tid & 31;
    int row0 = blockIdx.x * 8;
    int row = row0 + wid;
    const float4* gr = reinterpret_cast<const float4*>(graph + (size_t)row * NN);
    float s = 0.f;
    #pragma unroll 4
    for (int i = lane; i < NN / 4; i += 32) { float4 t = gr[i]; s += (t.x + t.y) + (t.z + t.w); }
    #pragma unroll
    for (int o = 16; o; o >>= 1) s += __shfl_xor_sync(0xffffffffu, s, o);
    if (lane == 0) { float nr = rsqrtf(fmaxf(s, 1.0f)); g_norm[row] = nr; nrm[wid] = nr; }
    int t0 = blockIdx.x * 256 + tid;
    g_target[t0] = 0.f; g_target[t0 + 196608] = 0.f;
    g_oacc[t0] = 0.f;   g_oacc[t0 + 196608] = 0.f;
    if (t0 < NN * 4) g_lacc[t0] = 0.f;
    const float* W = (row0 < NDRUG) ? drug_w : dis_w;
    for (int i = tid; i < 4096; i += 256) w[i] = W[i];
    for (int rep = 0; rep < 2; rep++) {
        int idx = rep * 256 + tid;
        int r = idx >> 6, d = idx & 63;
        int rr = row0 + r;
        fr[idx] = (row0 < NDRUG) ? drug_f[(size_t)rr * 64 + d]
                                 : dis_f[(size_t)(rr - NDRUG) * 64 + d];
    }
    __syncthreads();
    for (int rep = 0; rep < 2; rep++) {
        int idx = rep * 256 + tid;
        int r = idx >> 6, d = idx & 63;
        float acc = 0.f;
        #pragma unroll 16
        for (int k = 0; k < 64; k++) acc += fr[r * 64 + k] * w[k * 64 + d];
        g_xn[(size_t)(row0 + r) * 64 + d] = acc * nrm[r];
    }
}

// ===== K2: target += (graph @ xn) * row_norm via tf32 mma. grid (48,3), block 256 =====
#define AST 36
#define BST 72
__global__ __launch_bounds__(256) void k_spmm(const float* __restrict__ graph) {
    __shared__ __align__(16) float As[128 * AST];
    __shared__ __align__(16) float Bs[32 * BST];
    int tid = threadIdx.x;
    int w = tid >> 5, lane = tid & 31, g = lane >> 2, t = lane & 3;
    int rowbase = blockIdx.x * 128;
    int kstart = blockIdx.y * 2048;

    float o[8][4];
    #pragma unroll
    for (int nt = 0; nt < 8; nt++)
        #pragma unroll
        for (int i = 0; i < 4; i++) o[nt][i] = 0.f;

    int ar = tid >> 1, ac = (tid & 1) * 16;
    int br = tid >> 3, bc = (tid & 7) * 8;

    for (int kb = 0; kb < 2048; kb += 32) {
        const float* gp = graph + (size_t)(rowbase + ar) * NN + kstart + kb + ac;
        float4 a0 = *reinterpret_cast<const float4*>(gp);
        float4 a1 = *reinterpret_cast<const float4*>(gp + 4);
        float4 a2 = *reinterpret_cast<const float4*>(gp + 8);
        float4 a3 = *reinterpret_cast<const float4*>(gp + 12);
        const float* bp = g_xn + (size_t)(kstart + kb + br) * 64 + bc;
        float4 b0 = *reinterpret_cast<const float4*>(bp);
        float4 b1 = *reinterpret_cast<const float4*>(bp + 4);
        __syncthreads();
        *reinterpret_cast<float4*>(As + ar * AST + ac)      = a0;
        *reinterpret_cast<float4*>(As + ar * AST + ac + 4)  = a1;
        *reinterpret_cast<float4*>(As + ar * AST + ac + 8)  = a2;
        *reinterpret_cast<float4*>(As + ar * AST + ac + 12) = a3;
        *reinterpret_cast<float4*>(Bs + br * BST + bc)     = b0;
        *reinterpret_cast<float4*>(Bs + br * BST + bc + 4) = b1;
        __syncthreads();
        #pragma unroll
        for (int kc = 0; kc < 4; kc++) {
            unsigned a[4];
            a[0] = __float_as_uint(As[(w * 16 + g) * AST + kc * 8 + t]);
            a[1] = __float_as_uint(As[(w * 16 + g + 8) * AST + kc * 8 + t]);
            a[2] = __float_as_uint(As[(w * 16 + g) * AST + kc * 8 + t + 4]);
            a[3] = __float_as_uint(As[(w * 16 + g + 8) * AST + kc * 8 + t + 4]);
            #pragma unroll
            for (int nt = 0; nt < 8; nt++) {
                unsigned bb0 = __float_as_uint(Bs[(kc * 8 + t) * BST + nt * 8 + g]);
                unsigned bb1 = __float_as_uint(Bs[(kc * 8 + t + 4) * BST + nt * 8 + g]);
                MMA_TF32(o[nt], a, bb0, bb1);
            }
        }
    }
    int r0 = rowbase + w * 16 + g, r1 = r0 + 8;
    float n0 = g_norm[r0], n1 = g_norm[r1];
    #pragma unroll
    for (int nt = 0; nt < 8; nt++) {
        int c = nt * 8 + 2 * t;
        atomicAdd(&g_target[(size_t)r0 * 64 + c],     o[nt][0] * n0);
        atomicAdd(&g_target[(size_t)r0 * 64 + c + 1], o[nt][1] * n0);
        atomicAdd(&g_target[(size_t)r1 * 64 + c],     o[nt][2] * n1);
        atomicAdd(&g_target[(size_t)r1 * 64 + c + 1], o[nt][3] * n1);
    }
}

// ===== K3: time embedding + MLP -> aux. grid 768, block 256, 8 nodes/CTA =====
__global__ __launch_bounds__(256) void k_mlp(const int* __restrict__ tsteps,
                                             const float* __restrict__ emb_w, const float* __restrict__ emb_b,
                                             const float* __restrict__ in_w,  const float* __restrict__ in_b,
                                             const float* __restrict__ out_w, const float* __restrict__ out_b) {
    __shared__ float cs[8 * 81];
    __shared__ float hs[8 * 257];
    int tid = threadIdx.x;
    int base = blockIdx.x * 8;
    for (int idx = tid; idx < 8 * 64; idx += 256) {
        int n = idx >> 6, d = idx & 63;
        cs[n * 81 + d] = g_target[(size_t)(base + n) * 64 + d];
    }
    if (tid < 128) {
        int n = tid >> 4, e = tid & 15;
        float t = (float)tsteps[base + n];
        float acc = emb_b[e];
        for (int k = 0; k < 16; k++) {
            int j = k & 7;
            float fr = expf(-1.15129254649702f * (float)j);
            float te = (k < 8) ? cosf(t * fr) : sinf(t * fr);
            acc += te * emb_w[k * 16 + e];
        }
        cs[n * 81 + 64 + e] = acc;
    }
    __syncthreads();
    {
        float acc[8];
        #pragma unroll
        for (int n = 0; n < 8; n++) acc[n] = 0.f;
        #pragma unroll 4
        for (int k = 0; k < 80; k++) {
            float w = in_w[k * 256 + tid];
            #pragma unroll
            for (int n = 0; n < 8; n++) acc[n] += cs[n * 81 + k] * w;
        }
        float bj = in_b[tid];
        #pragma unroll
        for (int n = 0; n < 8; n++) hs[n * 257 + tid] = tanhf(acc[n] + bj);
    }
    __syncthreads();
    {
        int d = tid & 63, gg = tid >> 6;
        float oa0 = 0.f, oa1 = 0.f;
        #pragma unroll 4
        for (int k = 0; k < 256; k++) {
            float w = out_w[k * 64 + d];
            oa0 += hs[(gg * 2 + 0) * 257 + k] * w;
            oa1 += hs[(gg * 2 + 1) * 257 + k] * w;
        }
        float bd = out_b[d];
        g_aux[(size_t)(base + gg * 2 + 0) * 64 + d] = oa0 + bd;
        g_aux[(size_t)(base + gg * 2 + 1) * 64 + d] = oa1 + bd;
    }
}

// ===== K4: fused q/k/v via tf32 mma, N-split x2. grid (48,2), block 256, dyn smem 95744 B =====
#define QST 68
__global__ __launch_bounds__(256) void k_qkv(const float* __restrict__ wq, const float* __restrict__ bq,
                                             const float* __restrict__ wk, const float* __restrict__ bk,
                                             const float* __restrict__ wv, const float* __restrict__ bv) {
    extern __shared__ float qs[];
    float* At = qs;                   // 128*68
    float* Aa = qs + 128 * QST;       // 128*68
    float* Ws = qs + 256 * QST;       // 96*68 (transposed weight slice)
    __shared__ float bias[96];
    int tid = threadIdx.x;
    int w = tid >> 5, lane = tid & 31, g = lane >> 2, t = lane & 3;
    int row0 = blockIdx.x * 128;
    int ny = blockIdx.y;              // 0: cols 0..95, 1: cols 96..191

    for (int i = tid; i < 128 * 16; i += 256) {
        int r = i >> 4, c4 = (i & 15) * 4;
        float4 tv = *reinterpret_cast<const float4*>(g_target + (size_t)(row0 + r) * 64 + c4);
        float4 av = *reinterpret_cast<const float4*>(g_aux + (size_t)(row0 + r) * 64 + c4);
        float* td = At + r * QST + c4;
        td[0] = tv.x; td[1] = tv.y; td[2] = tv.z; td[3] = tv.w;
        float* ad = Aa + r * QST + c4;
        ad[0] = av.x; ad[1] = av.y; ad[2] = av.z; ad[3] = av.w;
    }
    for (int i = tid; i < 96 * 64; i += 256) {
        int k = i / 96, jl = i - k * 96;
        int jg = ny * 96 + jl;
        float val = (jg < 64) ? wq[k * 64 + jg]
                  : (jg < 128) ? wk[k * 64 + jg - 64]
                               : wv[k * 64 + jg - 128];
        Ws[jl * QST + k] = val;
    }
    if (tid < 96) {
        int jg = ny * 96 + tid;
        bias[tid] = (jg < 64) ? bq[jg] : (jg < 128) ? bk[jg - 64] : bv[jg - 128];
    }
    __syncthreads();

    float acc[12][4];
    #pragma unroll
    for (int nt = 0; nt < 12; nt++)
        #pragma unroll
        for (int i = 0; i < 4; i++) acc[nt][i] = 0.f;

    #pragma unroll
    for (int kc = 0; kc < 8; kc++) {
        unsigned at[4], aa[4];
        at[0] = __float_as_uint(At[(w * 16 + g) * QST + kc * 8 + t]);
        at[1] = __float_as_uint(At[(w * 16 + g + 8) * QST + kc * 8 + t]);
        at[2] = __float_as_uint(At[(w * 16 + g) * QST + kc * 8 + t + 4]);
        at[3] = __float_as_uint(At[(w * 16 + g + 8) * QST + kc * 8 + t + 4]);
        aa[0] = __float_as_uint(Aa[(w * 16 + g) * QST + kc * 8 + t]);
        aa[1] = __float_as_uint(Aa[(w * 16 + g + 8) * QST + kc * 8 + t]);
        aa[2] = __float_as_uint(Aa[(w * 16 + g) * QST + kc * 8 + t + 4]);
        aa[3] = __float_as_uint(Aa[(w * 16 + g + 8) * QST + kc * 8 + t + 4]);
        #pragma unroll
        for (int nt = 0; nt < 12; nt++) {
            unsigned b0 = __float_as_uint(Ws[(nt * 8 + g) * QST + kc * 8 + t]);
            unsigned b1 = __float_as_uint(Ws[(nt * 8 + g) * QST + kc * 8 + t + 4]);
            bool useT = (ny == 0 && nt < 8);   // q cols come from target
            MMA_TF32(acc[nt], useT ? at : aa, b0, b1);
        }
    }

    int r0 = row0 + w * 16 + g, r1 = r0 + 8;
    #pragma unroll
    for (int nt = 0; nt < 12; nt++) {
        int jj = ny * 96 + nt * 8 + 2 * t;
        float b0 = bias[nt * 8 + 2 * t], b1 = bias[nt * 8 + 2 * t + 1];
        #pragma unroll
        for (int e = 0; e < 2; e++) {
            int jg = jj + e;
            int sel = jg >> 6, jl = jg & 63;
            float* D = (sel == 0) ? g_q : (sel == 1) ? g_k : g_v;
            int hh = jl >> 4, hd = jl & 15;
            float bb = e ? b1 : b0;
            D[((size_t)hh * NN + r0) * 16 + hd] = acc[nt][e] + bb;
            D[((size_t)hh * NN + r1) * 16 + hd] = acc[nt][2 + e] + bb;
        }
    }
}

// ===== K5: attention, tf32 mma + register-shuffle P. grid (24,4,3), block 256 =====
#define KS_STR 20
#define VS_STR 25
__global__ __launch_bounds__(256) void k_attn() {
    __shared__ float Ks[64 * KS_STR];
    __shared__ float Vsb[64 * VS_STR];
    int tid = threadIdx.x;
    int w = tid >> 5, lane = tid & 31;
    int g = lane >> 2, t = lane & 3;
    int h = blockIdx.y;
    int qn0 = blockIdx.x * 256 + w * 32;

    // constant V columns: col 16 = 1 (gives l), 17..24 = 0
    for (int idx = tid; idx < 64 * 9; idx += 256) {
        int row = idx / 9, c = 16 + idx % 9;
        Vsb[row * VS_STR + c] = (c == 16) ? 1.0f : 0.0f;
    }

    const float* qb = g_q + ((size_t)h * NN + qn0) * 16;
    unsigned aq[2][2][4];
    #pragma unroll
    for (int mt = 0; mt < 2; mt++)
        #pragma unroll
        for (int kc = 0; kc < 2; kc++) {
            aq[mt][kc][0] = __float_as_uint(0.25f * qb[(mt * 16 + g) * 16 + kc * 8 + t]);
            aq[mt][kc][1] = __float_as_uint(0.25f * qb[(mt * 16 + g + 8) * 16 + kc * 8 + t]);
            aq[mt][kc][2] = __float_as_uint(0.25f * qb[(mt * 16 + g) * 16 + kc * 8 + t + 4]);
            aq[mt][kc][3] = __float_as_uint(0.25f * qb[(mt * 16 + g + 8) * 16 + kc * 8 + t + 4]);
        }

    float o[2][3][4];
    #pragma unroll
    for (int mt = 0; mt < 2; mt++)
        #pragma unroll
        for (int nt = 0; nt < 3; nt++)
            #pragma unroll
            for (int i = 0; i < 4; i++) o[mt][nt][i] = 0.f;

    int kbase = blockIdx.z * 2048;
    int krow = tid >> 2, kq = tid & 3;
    int srcA = (lane & ~3) | ((lane & 3) >> 1);
    int srcB = srcA + 2;
    bool odd = (t & 1);

    // prefetch first K/V block
    float4 kv = *reinterpret_cast<const float4*>(g_k + ((size_t)h * NN + kbase + krow) * 16 + kq * 4);
    float4 vv = *reinterpret_cast<const float4*>(g_v + ((size_t)h * NN + kbase + krow) * 16 + kq * 4);

    for (int c0 = 0; c0 < 2048; c0 += 64) {
        __syncthreads();
        *reinterpret_cast<float4*>(Ks + krow * KS_STR + kq * 4) = kv;
        {
            float* vd = Vsb + krow * VS_STR + kq * 4;
            vd[0] = vv.x; vd[1] = vv.y; vd[2] = vv.z; vd[3] = vv.w;
        }
        __syncthreads();
        if (c0 + 64 < 2048) {
            int key = kbase + c0 + 64 + krow;
            kv = *reinterpret_cast<const float4*>(g_k + ((size_t)h * NN + key) * 16 + kq * 4);
            vv = *reinterpret_cast<const float4*>(g_v + ((size_t)h * NN + key) * 16 + kq * 4);
        }

        #pragma unroll
        for (int nt = 0; nt < 8; nt++) {
            float d0[4] = {0.f, 0.f, 0.f, 0.f};
            float d1[4] = {0.f, 0.f, 0.f, 0.f};
            #pragma unroll
            for (int kc = 0; kc < 2; kc++) {
                unsigned b0 = __float_as_uint(Ks[(nt * 8 + g) * KS_STR + kc * 8 + t]);
                unsigned b1 = __float_as_uint(Ks[(nt * 8 + g) * KS_STR + kc * 8 + t + 4]);
                MMA_TF32(d0, aq[0][kc], b0, b1);
                MMA_TF32(d1, aq[1][kc], b0, b1);
            }
            // exp (scores pre-scaled by 0.25 via Q)
            #pragma unroll
            for (int i = 0; i < 4; i++) { d0[i] = __expf(d0[i]); d1[i] = __expf(d1[i]); }
            // permute C-fragment -> A-fragment for PV
            unsigned pa0[4], pa1[4];
            {
                float x0 = __shfl_sync(0xffffffffu, d0[0], srcA);
                float x1 = __shfl_sync(0xffffffffu, d0[1], srcA);
                float y0 = __shfl_sync(0xffffffffu, d0[2], srcA);
                float y1 = __shfl_sync(0xffffffffu, d0[3], srcA);
                float z0 = __shfl_sync(0xffffffffu, d0[0], srcB);
                float z1 = __shfl_sync(0xffffffffu, d0[1], srcB);
                float u0 = __shfl_sync(0xffffffffu, d0[2], srcB);
                float u1 = __shfl_sync(0xffffffffu, d0[3], srcB);
                pa0[0] = __float_as_uint(odd ? x1 : x0);
                pa0[1] = __float_as_uint(odd ? y1 : y0);
                pa0[2] = __float_as_uint(odd ? z1 : z0);
                pa0[3] = __float_as_uint(odd ? u1 : u0);
            }
            {
                float x0 = __shfl_sync(0xffffffffu, d1[0], srcA);
                float x1 = __shfl_sync(0xffffffffu, d1[1], srcA);
                float y0 = __shfl_sync(0xffffffffu, d1[2], srcA);
                float y1 = __shfl_sync(0xffffffffu, d1[3], srcA);
                float z0 = __shfl_sync(0xffffffffu, d1[0], srcB);
                float z1 = __shfl_sync(0xffffffffu, d1[1], srcB);
                float u0 = __shfl_sync(0xffffffffu, d1[2], srcB);
                float u1 = __shfl_sync(0xffffffffu, d1[3], srcB);
                pa1[0] = __float_as_uint(odd ? x1 : x0);
                pa1[1] = __float_as_uint(odd ? y1 : y0);
                pa1[2] = __float_as_uint(odd ? z1 : z0);
                pa1[3] = __float_as_uint(odd ? u1 : u0);
            }
            // O += P V (V col 16 is ones -> denominators)
            #pragma unroll
            for (int vt = 0; vt < 3; vt++) {
                unsigned b0 = __float_as_uint(Vsb[(nt * 8 + t) * VS_STR + vt * 8 + g]);
                unsigned b1 = __float_as_uint(Vsb[(nt * 8 + t + 4) * VS_STR + vt * 8 + g]);
                MMA_TF32(o[0][vt], pa0, b0, b1);
                MMA_TF32(o[1][vt], pa1, b0, b1);
            }
        }
    }

    #pragma unroll
    for (int mt = 0; mt < 2; mt++) {
        int r0 = qn0 + mt * 16 + g, r1 = r0 + 8;
        #pragma unroll
        for (int nt = 0; nt < 2; nt++) {
            int c = h * 16 + nt * 8 + 2 * t;
            atomicAdd(&g_oacc[(size_t)r0 * 64 + c],     o[mt][nt][0]);
            atomicAdd(&g_oacc[(size_t)r0 * 64 + c + 1], o[mt][nt][1]);
            atomicAdd(&g_oacc[(size_t)r1 * 64 + c],     o[mt][nt][2]);
            atomicAdd(&g_oacc[(size_t)r1 * 64 + c + 1], o[mt][nt][3]);
        }
        if (t == 0) {
            atomicAdd(&g_lacc[r0 * 4 + h], o[mt][2][0]);
            atomicAdd(&g_lacc[r1 * 4 + h], o[mt][2][2]);
        }
    }
}

// ===== K6: wo proj + fuse + residual LN -> out. grid 1536, block 256 =====
__global__ __launch_bounds__(256) void k_final(const float* __restrict__ wo, const float* __restrict__ bo,
                                               const float* __restrict__ fuse_w, const float* __restrict__ fuse_b,
                                               const float* __restrict__ ln_g, const float* __restrict__ ln_b,
                                               float* __restrict__ out) {
    __shared__ float w[4096];
    __shared__ float st[256], sao[256], sy[256];
    int r = threadIdx.x >> 6, d = threadIdx.x & 63;
    int row = blockIdx.x * 4 + r;
    st[r * 64 + d] = g_target[(size_t)row * 64 + d];
    float lh = g_lacc[row * 4 + (d >> 4)];
    sy[r * 64 + d] = g_oacc[(size_t)row * 64 + d] / lh;
    for (int i = threadIdx.x; i < 4096; i += 256) w[i] = wo[i];
    __syncthreads();
    float acc = bo[d];
    #pragma unroll 16
    for (int k = 0; k < 64; k++) acc += sy[r * 64 + k] * w[k * 64 + d];
    __syncthreads();
    sao[r * 64 + d] = acc;
    for (int i = threadIdx.x; i < 4096; i += 256) w[i] = fuse_w[i];
    __syncthreads();
    float f = fuse_b[d];
    #pragma unroll 16
    for (int k = 0; k < 64; k++) f += st[r * 64 + k] * w[k * 64 + d];
    __syncthreads();
    for (int i = threadIdx.x; i < 4096; i += 256) w[i] = fuse_w[4096 + i];
    __syncthreads();
    #pragma unroll 16
    for (int k = 0; k < 64; k++) f += sao[r * 64 + k] * w[k * 64 + d];
    float y = f + st[r * 64 + d];
    __syncthreads();
    sy[r * 64 + d] = y;
    __syncthreads();
    float mu = 0.f;
    #pragma unroll 16
    for (int k = 0; k < 64; k++) mu += sy[r * 64 + k];
    mu *= (1.0f / 64.0f);
    float var = 0.f;
    #pragma unroll 16
    for (int k = 0; k < 64; k++) { float tt = sy[r * 64 + k] - mu; var += tt * tt; }
    var *= (1.0f / 64.0f);
    out[(size_t)row * 64 + d] = (y - mu) * rsqrtf(var + 1e-5f) * ln_g[d] + ln_b[d];
}

extern "C" void kernel_launch(void* const* d_in, const int* in_sizes, int n_in,
                              void* d_out, int out_size) {
    const float* graph     = (const float*)d_in[0];
    const float* drug_f    = (const float*)d_in[1];
    const float* disease_f = (const float*)d_in[2];
    const int*   tsteps    = (const int*)  d_in[3];
    const float* drug_w    = (const float*)d_in[4];
    const float* disease_w = (const float*)d_in[5];
    const float* emb_w     = (const float*)d_in[6];
    const float* emb_b     = (const float*)d_in[7];
    const float* in_w      = (const float*)d_in[8];
    const float* in_b      = (const float*)d_in[9];
    const float* out_w     = (const float*)d_in[10];
    const float* out_b     = (const float*)d_in[11];
    const float* wq = (const float*)d_in[12]; const float* bq = (const float*)d_in[13];
    const float* wk = (const float*)d_in[14]; const float* bk = (const float*)d_in[15];
    const float* wv = (const float*)d_in[16]; const float* bv = (const float*)d_in[17];
    const float* wo = (const float*)d_in[18]; const float* bo = (const float*)d_in[19];
    const float* fuse_w = (const float*)d_in[20]; const float* fuse_b = (const float*)d_in[21];
    const float* ln_g   = (const float*)d_in[22]; const float* ln_b   = (const float*)d_in[23];
    float* out = (float*)d_out;

    static int attr_set = 0;
    if (!attr_set) {
        cudaFuncSetAttribute(k_qkv, cudaFuncAttributeMaxDynamicSharedMemorySize, 95744);
        attr_set = 1;
    }

    k_degproj<<<768, 256>>>(graph, drug_f, disease_f, drug_w, disease_w);
    k_spmm   <<<dim3(48, 3), 256>>>(graph);
    k_mlp    <<<768, 256>>>(tsteps, emb_w, emb_b, in_w, in_b, out_w, out_b);
    k_qkv    <<<dim3(48, 2), 256, 95744>>>(wq, bq, wk, bk, wv, bv);
    k_attn   <<<dim3(24, 4, 3), 256>>>();
    k_final  <<<1536, 256>>>(wo, bo, fuse_w, fuse_b, ln_g, ln_b, out);
}

// round 14
// speedup vs baseline: 1.0606x; 1.0606x over previous
#include <cuda_runtime.h>
#include <math.h>

#define NN 6144
#define NDRUG 3072

// ---------- scratch (device globals; no allocation allowed) ----------
__device__ __align__(16) float g_norm[NN];
__device__ __align__(16) float g_xn[NN * 64];
__device__ __align__(16) float g_target[NN * 64];
__device__ __align__(16) float g_aux[NN * 64];
__device__ __align__(16) float g_q[4 * NN * 16];    // head-major
__device__ __align__(16) float g_k[4 * NN * 16];
__device__ __align__(16) float g_v[4 * NN * 16];
__device__ __align__(16) float g_oacc[NN * 64];
__device__ __align__(16) float g_lacc[NN * 4];

#define MMA_TF32(D, A, B0, B1) \
    asm volatile("mma.sync.aligned.m16n8k8.row.col.f32.tf32.tf32.f32 " \
                 "{%0,%1,%2,%3},{%4,%5,%6,%7},{%8,%9},{%0,%1,%2,%3};" \
                 : "+f"((D)[0]), "+f"((D)[1]), "+f"((D)[2]), "+f"((D)[3]) \
                 : "r"((A)[0]), "r"((A)[1]), "r"((A)[2]), "r"((A)[3]), "r"(B0), "r"(B1))

// ===== K1: degree norms + per-type projection + zero accumulators. grid 768, block 256 =====
__global__ __launch_bounds__(256) void k_degproj(const float* __restrict__ graph,
                                                 const float* __restrict__ drug_f,
                                                 const float* __restrict__ dis_f,
                                                 const float* __restrict__ drug_w,
                                                 const float* __restrict__ dis_w) {
    __shared__ float w[4096];
    __shared__ float fr[512];
    __shared__ float nrm[8];
    int tid = threadIdx.x;
    int wid = tid >> 5, lane = tid & 31;
    int row0 = blockIdx.x * 8;
    int row = row0 + wid;
    const float4* gr = reinterpret_cast<const float4*>(graph + (size_t)row * NN);
    float s = 0.f;
    #pragma unroll 4
    for (int i = lane; i < NN / 4; i += 32) { float4 t = gr[i]; s += (t.x + t.y) + (t.z + t.w); }
    #pragma unroll
    for (int o = 16; o; o >>= 1) s += __shfl_xor_sync(0xffffffffu, s, o);
    if (lane == 0) { float nr = rsqrtf(fmaxf(s, 1.0f)); g_norm[row] = nr; nrm[wid] = nr; }
    int t0 = blockIdx.x * 256 + tid;
    g_target[t0] = 0.f; g_target[t0 + 196608] = 0.f;
    g_oacc[t0] = 0.f;   g_oacc[t0 + 196608] = 0.f;
    if (t0 < NN * 4) g_lacc[t0] = 0.f;
    const float* W = (row0 < NDRUG) ? drug_w : dis_w;
    for (int i = tid; i < 4096; i += 256) w[i] = W[i];
    for (int rep = 0; rep < 2; rep++) {
        int idx = rep * 256 + tid;
        int r = idx >> 6, d = idx & 63;
        int rr = row0 + r;
        fr[idx] = (row0 < NDRUG) ? drug_f[(size_t)rr * 64 + d]
                                 : dis_f[(size_t)(rr - NDRUG) * 64 + d];
    }
    __syncthreads();
    for (int rep = 0; rep < 2; rep++) {
        int idx = rep * 256 + tid;
        int r = idx >> 6, d = idx & 63;
        float acc = 0.f;
        #pragma unroll 16
        for (int k = 0; k < 64; k++) acc += fr[r * 64 + k] * w[k * 64 + d];
        g_xn[(size_t)(row0 + r) * 64 + d] = acc * nrm[r];
    }
}

// ===== K2: target += (graph @ xn) * row_norm via tf32 mma. grid (48,3), block 256 =====
#define AST 36
#define BST 72
__global__ __launch_bounds__(256) void k_spmm(const float* __restrict__ graph) {
    __shared__ __align__(16) float As[128 * AST];
    __shared__ __align__(16) float Bs[32 * BST];
    int tid = threadIdx.x;
    int w = tid >> 5, lane = tid & 31, g = lane >> 2, t = lane & 3;
    int rowbase = blockIdx.x * 128;
    int kstart = blockIdx.y * 2048;

    float o[8][4];
    #pragma unroll
    for (int nt = 0; nt < 8; nt++)
        #pragma unroll
        for (int i = 0; i < 4; i++) o[nt][i] = 0.f;

    int ar = tid >> 1, ac = (tid & 1) * 16;
    int br = tid >> 3, bc = (tid & 7) * 8;

    for (int kb = 0; kb < 2048; kb += 32) {
        const float* gp = graph + (size_t)(rowbase + ar) * NN + kstart + kb + ac;
        float4 a0 = *reinterpret_cast<const float4*>(gp);
        float4 a1 = *reinterpret_cast<const float4*>(gp + 4);
        float4 a2 = *reinterpret_cast<const float4*>(gp + 8);
        float4 a3 = *reinterpret_cast<const float4*>(gp + 12);
        const float* bp = g_xn + (size_t)(kstart + kb + br) * 64 + bc;
        float4 b0 = *reinterpret_cast<const float4*>(bp);
        float4 b1 = *reinterpret_cast<const float4*>(bp + 4);
        __syncthreads();
        *reinterpret_cast<float4*>(As + ar * AST + ac)      = a0;
        *reinterpret_cast<float4*>(As + ar * AST + ac + 4)  = a1;
        *reinterpret_cast<float4*>(As + ar * AST + ac + 8)  = a2;
        *reinterpret_cast<float4*>(As + ar * AST + ac + 12) = a3;
        *reinterpret_cast<float4*>(Bs + br * BST + bc)     = b0;
        *reinterpret_cast<float4*>(Bs + br * BST + bc + 4) = b1;
        __syncthreads();
        #pragma unroll
        for (int kc = 0; kc < 4; kc++) {
            unsigned a[4];
            a[0] = __float_as_uint(As[(w * 16 + g) * AST + kc * 8 + t]);
            a[1] = __float_as_uint(As[(w * 16 + g + 8) * AST + kc * 8 + t]);
            a[2] = __float_as_uint(As[(w * 16 + g) * AST + kc * 8 + t + 4]);
            a[3] = __float_as_uint(As[(w * 16 + g + 8) * AST + kc * 8 + t + 4]);
            #pragma unroll
            for (int nt = 0; nt < 8; nt++) {
                unsigned bb0 = __float_as_uint(Bs[(kc * 8 + t) * BST + nt * 8 + g]);
                unsigned bb1 = __float_as_uint(Bs[(kc * 8 + t + 4) * BST + nt * 8 + g]);
                MMA_TF32(o[nt], a, bb0, bb1);
            }
        }
    }
    int r0 = rowbase + w * 16 + g, r1 = r0 + 8;
    float n0 = g_norm[r0], n1 = g_norm[r1];
    #pragma unroll
    for (int nt = 0; nt < 8; nt++) {
        int c = nt * 8 + 2 * t;
        atomicAdd(&g_target[(size_t)r0 * 64 + c],     o[nt][0] * n0);
        atomicAdd(&g_target[(size_t)r0 * 64 + c + 1], o[nt][1] * n0);
        atomicAdd(&g_target[(size_t)r1 * 64 + c],     o[nt][2] * n1);
        atomicAdd(&g_target[(size_t)r1 * 64 + c + 1], o[nt][3] * n1);
    }
}

// ===== K3: time embedding + MLP -> aux. grid 768, block 256, 8 nodes/CTA =====
__global__ __launch_bounds__(256) void k_mlp(const int* __restrict__ tsteps,
                                             const float* __restrict__ emb_w, const float* __restrict__ emb_b,
                                             const float* __restrict__ in_w,  const float* __restrict__ in_b,
                                             const float* __restrict__ out_w, const float* __restrict__ out_b) {
    __shared__ float cs[8 * 81];
    __shared__ float hs[8 * 257];
    int tid = threadIdx.x;
    int base = blockIdx.x * 8;
    for (int idx = tid; idx < 8 * 64; idx += 256) {
        int n = idx >> 6, d = idx & 63;
        cs[n * 81 + d] = g_target[(size_t)(base + n) * 64 + d];
    }
    if (tid < 128) {
        int n = tid >> 4, e = tid & 15;
        float t = (float)tsteps[base + n];
        float acc = emb_b[e];
        for (int k = 0; k < 16; k++) {
            int j = k & 7;
            float fr = expf(-1.15129254649702f * (float)j);
            float te = (k < 8) ? cosf(t * fr) : sinf(t * fr);
            acc += te * emb_w[k * 16 + e];
        }
        cs[n * 81 + 64 + e] = acc;
    }
    __syncthreads();
    {
        float acc[8];
        #pragma unroll
        for (int n = 0; n < 8; n++) acc[n] = 0.f;
        #pragma unroll 4
        for (int k = 0; k < 80; k++) {
            float w = in_w[k * 256 + tid];
            #pragma unroll
            for (int n = 0; n < 8; n++) acc[n] += cs[n * 81 + k] * w;
        }
        float bj = in_b[tid];
        #pragma unroll
        for (int n = 0; n < 8; n++) hs[n * 257 + tid] = tanhf(acc[n] + bj);
    }
    __syncthreads();
    {
        int d = tid & 63, gg = tid >> 6;
        float oa0 = 0.f, oa1 = 0.f;
        #pragma unroll 4
        for (int k = 0; k < 256; k++) {
            float w = out_w[k * 64 + d];
            oa0 += hs[(gg * 2 + 0) * 257 + k] * w;
            oa1 += hs[(gg * 2 + 1) * 257 + k] * w;
        }
        float bd = out_b[d];
        g_aux[(size_t)(base + gg * 2 + 0) * 64 + d] = oa0 + bd;
        g_aux[(size_t)(base + gg * 2 + 1) * 64 + d] = oa1 + bd;
    }
}

// ===== K4: fused q/k/v projections via tf32 mma. grid 48, block 256, dyn smem 121856 B =====
#define QST 68
__global__ __launch_bounds__(256) void k_qkv(const float* __restrict__ wq, const float* __restrict__ bq,
                                             const float* __restrict__ wk, const float* __restrict__ bk,
                                             const float* __restrict__ wv, const float* __restrict__ bv) {
    extern __shared__ float qs[];
    float* At = qs;                   // 128*68
    float* Aa = qs + 128 * QST;       // 128*68
    float* Ws = qs + 256 * QST;       // 192*68 (transposed weights)
    __shared__ float bias[192];
    int tid = threadIdx.x;
    int w = tid >> 5, lane = tid & 31, g = lane >> 2, t = lane & 3;
    int row0 = blockIdx.x * 128;

    for (int i = tid; i < 128 * 16; i += 256) {
        int r = i >> 4, c4 = (i & 15) * 4;
        float4 tv = *reinterpret_cast<const float4*>(g_target + (size_t)(row0 + r) * 64 + c4);
        float4 av = *reinterpret_cast<const float4*>(g_aux + (size_t)(row0 + r) * 64 + c4);
        float* td = At + r * QST + c4;
        td[0] = tv.x; td[1] = tv.y; td[2] = tv.z; td[3] = tv.w;
        float* ad = Aa + r * QST + c4;
        ad[0] = av.x; ad[1] = av.y; ad[2] = av.z; ad[3] = av.w;
    }
    for (int i = tid; i < 4096; i += 256) {
        int k = i >> 6, d = i & 63;
        Ws[d * QST + k]         = wq[i];
        Ws[(64 + d) * QST + k]  = wk[i];
        Ws[(128 + d) * QST + k] = wv[i];
    }
    if (tid < 192) bias[tid] = (tid < 64) ? bq[tid] : (tid < 128) ? bk[tid - 64] : bv[tid - 128];
    __syncthreads();

    float acc[24][4];
    #pragma unroll
    for (int nt = 0; nt < 24; nt++)
        #pragma unroll
        for (int i = 0; i < 4; i++) acc[nt][i] = 0.f;

    #pragma unroll
    for (int kc = 0; kc < 8; kc++) {
        unsigned at[4], aa[4];
        at[0] = __float_as_uint(At[(w * 16 + g) * QST + kc * 8 + t]);
        at[1] = __float_as_uint(At[(w * 16 + g + 8) * QST + kc * 8 + t]);
        at[2] = __float_as_uint(At[(w * 16 + g) * QST + kc * 8 + t + 4]);
        at[3] = __float_as_uint(At[(w * 16 + g + 8) * QST + kc * 8 + t + 4]);
        aa[0] = __float_as_uint(Aa[(w * 16 + g) * QST + kc * 8 + t]);
        aa[1] = __float_as_uint(Aa[(w * 16 + g + 8) * QST + kc * 8 + t]);
        aa[2] = __float_as_uint(Aa[(w * 16 + g) * QST + kc * 8 + t + 4]);
        aa[3] = __float_as_uint(Aa[(w * 16 + g + 8) * QST + kc * 8 + t + 4]);
        #pragma unroll
        for (int nt = 0; nt < 24; nt++) {
            unsigned b0 = __float_as_uint(Ws[(nt * 8 + g) * QST + kc * 8 + t]);
            unsigned b1 = __float_as_uint(Ws[(nt * 8 + g) * QST + kc * 8 + t + 4]);
            MMA_TF32(acc[nt], (nt < 8) ? at : aa, b0, b1);
        }
    }

    int r0 = row0 + w * 16 + g, r1 = r0 + 8;
    #pragma unroll
    for (int nt = 0; nt < 24; nt++) {
        int jj = nt * 8 + 2 * t;
        int sel = jj >> 6, jl = jj & 63;
        float* D = (sel == 0) ? g_q : (sel == 1) ? g_k : g_v;
        int h = jl >> 4, hd = jl & 15;
        int h2 = (jl + 1) >> 4, hd2 = (jl + 1) & 15;
        float b0 = bias[jj], b1 = bias[jj + 1];
        D[((size_t)h * NN + r0) * 16 + hd]   = acc[nt][0] + b0;
        D[((size_t)h2 * NN + r0) * 16 + hd2] = acc[nt][1] + b1;
        D[((size_t)h * NN + r1) * 16 + hd]   = acc[nt][2] + b0;
        D[((size_t)h2 * NN + r1) * 16 + hd2] = acc[nt][3] + b1;
    }
}

// ===== K5: attention, tf32 mma, shuffle-P, register-l. grid (24,4,3), block 256 =====
#define KS_STR 20
#define VS_STR 25
__global__ __launch_bounds__(256) void k_attn() {
    __shared__ float Ks[64 * KS_STR];
    __shared__ float Vsb[64 * VS_STR];
    int tid = threadIdx.x;
    int w = tid >> 5, lane = tid & 31;
    int g = lane >> 2, t = lane & 3;
    int h = blockIdx.y;
    int qn0 = blockIdx.x * 256 + w * 32;

    const float* qb = g_q + ((size_t)h * NN + qn0) * 16;
    unsigned aq[2][2][4];
    #pragma unroll
    for (int mt = 0; mt < 2; mt++)
        #pragma unroll
        for (int kc = 0; kc < 2; kc++) {
            aq[mt][kc][0] = __float_as_uint(0.25f * qb[(mt * 16 + g) * 16 + kc * 8 + t]);
            aq[mt][kc][1] = __float_as_uint(0.25f * qb[(mt * 16 + g + 8) * 16 + kc * 8 + t]);
            aq[mt][kc][2] = __float_as_uint(0.25f * qb[(mt * 16 + g) * 16 + kc * 8 + t + 4]);
            aq[mt][kc][3] = __float_as_uint(0.25f * qb[(mt * 16 + g + 8) * 16 + kc * 8 + t + 4]);
        }

    float o[2][2][4];
    #pragma unroll
    for (int mt = 0; mt < 2; mt++)
        #pragma unroll
        for (int nt = 0; nt < 2; nt++)
            #pragma unroll
            for (int i = 0; i < 4; i++) o[mt][nt][i] = 0.f;
    float ls[2][2] = {{0.f, 0.f}, {0.f, 0.f}};   // [mt][row-half] softmax denominators

    int kbase = blockIdx.z * 2048;
    int krow = tid >> 2, kq = tid & 3;
    int srcA = (lane & ~3) | ((lane & 3) >> 1);
    int srcB = srcA + 2;
    bool odd = (t & 1);

    float4 kv = *reinterpret_cast<const float4*>(g_k + ((size_t)h * NN + kbase + krow) * 16 + kq * 4);
    float4 vv = *reinterpret_cast<const float4*>(g_v + ((size_t)h * NN + kbase + krow) * 16 + kq * 4);

    for (int c0 = 0; c0 < 2048; c0 += 64) {
        __syncthreads();
        *reinterpret_cast<float4*>(Ks + krow * KS_STR + kq * 4) = kv;
        {
            float* vd = Vsb + krow * VS_STR + kq * 4;
            vd[0] = vv.x; vd[1] = vv.y; vd[2] = vv.z; vd[3] = vv.w;
        }
        __syncthreads();
        if (c0 + 64 < 2048) {
            int key = kbase + c0 + 64 + krow;
            kv = *reinterpret_cast<const float4*>(g_k + ((size_t)h * NN + key) * 16 + kq * 4);
            vv = *reinterpret_cast<const float4*>(g_v + ((size_t)h * NN + key) * 16 + kq * 4);
        }

        #pragma unroll
        for (int nt = 0; nt < 8; nt++) {
            float d0[4] = {0.f, 0.f, 0.f, 0.f};
            float d1[4] = {0.f, 0.f, 0.f, 0.f};
            #pragma unroll
            for (int kc = 0; kc < 2; kc++) {
                unsigned b0 = __float_as_uint(Ks[(nt * 8 + g) * KS_STR + kc * 8 + t]);
                unsigned b1 = __float_as_uint(Ks[(nt * 8 + g) * KS_STR + kc * 8 + t + 4]);
                MMA_TF32(d0, aq[0][kc], b0, b1);
                MMA_TF32(d1, aq[1][kc], b0, b1);
            }
            #pragma unroll
            for (int i = 0; i < 4; i++) { d0[i] = __expf(d0[i]); d1[i] = __expf(d1[i]); }
            ls[0][0] += d0[0] + d0[1]; ls[0][1] += d0[2] + d0[3];
            ls[1][0] += d1[0] + d1[1]; ls[1][1] += d1[2] + d1[3];
            unsigned pa0[4], pa1[4];
            {
                float x0 = __shfl_sync(0xffffffffu, d0[0], srcA);
                float x1 = __shfl_sync(0xffffffffu, d0[1], srcA);
                float y0 = __shfl_sync(0xffffffffu, d0[2], srcA);
                float y1 = __shfl_sync(0xffffffffu, d0[3], srcA);
                float z0 = __shfl_sync(0xffffffffu, d0[0], srcB);
                float z1 = __shfl_sync(0xffffffffu, d0[1], srcB);
                float u0 = __shfl_sync(0xffffffffu, d0[2], srcB);
                float u1 = __shfl_sync(0xffffffffu, d0[3], srcB);
                pa0[0] = __float_as_uint(odd ? x1 : x0);
                pa0[1] = __float_as_uint(odd ? y1 : y0);
                pa0[2] = __float_as_uint(odd ? z1 : z0);
                pa0[3] = __float_as_uint(odd ? u1 : u0);
            }
            {
                float x0 = __shfl_sync(0xffffffffu, d1[0], srcA);
                float x1 = __shfl_sync(0xffffffffu, d1[1], srcA);
                float y0 = __shfl_sync(0xffffffffu, d1[2], srcA);
                float y1 = __shfl_sync(0xffffffffu, d1[3], srcA);
                float z0 = __shfl_sync(0xffffffffu, d1[0], srcB);
                float z1 = __shfl_sync(0xffffffffu, d1[1], srcB);
                float u0 = __shfl_sync(0xffffffffu, d1[2], srcB);
                float u1 = __shfl_sync(0xffffffffu, d1[3], srcB);
                pa1[0] = __float_as_uint(odd ? x1 : x0);
                pa1[1] = __float_as_uint(odd ? y1 : y0);
                pa1[2] = __float_as_uint(odd ? z1 : z0);
                pa1[3] = __float_as_uint(odd ? u1 : u0);
            }
            #pragma unroll
            for (int vt = 0; vt < 2; vt++) {
                unsigned b0 = __float_as_uint(Vsb[(nt * 8 + t) * VS_STR + vt * 8 + g]);
                unsigned b1 = __float_as_uint(Vsb[(nt * 8 + t + 4) * VS_STR + vt * 8 + g]);
                MMA_TF32(o[0][vt], pa0, b0, b1);
                MMA_TF32(o[1][vt], pa1, b0, b1);
            }
        }
    }

    #pragma unroll
    for (int mt = 0; mt < 2; mt++)
        #pragma unroll
        for (int i = 0; i < 2; i++) {
            ls[mt][i] += __shfl_xor_sync(0xffffffffu, ls[mt][i], 1);
            ls[mt][i] += __shfl_xor_sync(0xffffffffu, ls[mt][i], 2);
        }

    #pragma unroll
    for (int mt = 0; mt < 2; mt++) {
        int r0 = qn0 + mt * 16 + g, r1 = r0 + 8;
        #pragma unroll
        for (int nt = 0; nt < 2; nt++) {
            int c = h * 16 + nt * 8 + 2 * t;
            atomicAdd(&g_oacc[(size_t)r0 * 64 + c],     o[mt][nt][0]);
            atomicAdd(&g_oacc[(size_t)r0 * 64 + c + 1], o[mt][nt][1]);
            atomicAdd(&g_oacc[(size_t)r1 * 64 + c],     o[mt][nt][2]);
            atomicAdd(&g_oacc[(size_t)r1 * 64 + c + 1], o[mt][nt][3]);
        }
        if (t == 0) {
            atomicAdd(&g_lacc[r0 * 4 + h], ls[mt][0]);
            atomicAdd(&g_lacc[r1 * 4 + h], ls[mt][1]);
        }
    }
}

// ===== K6: wo proj + fuse + residual LN -> out. grid 1536, block 256, dyn smem 49152 =====
__global__ __launch_bounds__(256) void k_final(const float* __restrict__ wo, const float* __restrict__ bo,
                                               const float* __restrict__ fuse_w, const float* __restrict__ fuse_b,
                                               const float* __restrict__ ln_g, const float* __restrict__ ln_b,
                                               float* __restrict__ out) {
    extern __shared__ float fsm[];
    float* wo_s = fsm;          // 4096
    float* fw   = fsm + 4096;   // 8192
    __shared__ float st[256], sao[256], sy[256];
    int r = threadIdx.x >> 6, d = threadIdx.x & 63;
    int row = blockIdx.x * 4 + r;
    for (int i = threadIdx.x; i < 4096 / 4; i += 256)
        reinterpret_cast<float4*>(wo_s)[i] = reinterpret_cast<const float4*>(wo)[i];
    for (int i = threadIdx.x; i < 8192 / 4; i += 256)
        reinterpret_cast<float4*>(fw)[i] = reinterpret_cast<const float4*>(fuse_w)[i];
    st[r * 64 + d] = g_target[(size_t)row * 64 + d];
    float lh = g_lacc[row * 4 + (d >> 4)];
    sy[r * 64 + d] = g_oacc[(size_t)row * 64 + d] / lh;
    __syncthreads();
    float acc = bo[d];
    #pragma unroll 16
    for (int k = 0; k < 64; k++) acc += sy[r * 64 + k] * wo_s[k * 64 + d];
    sao[r * 64 + d] = acc;
    __syncthreads();
    float f = fuse_b[d];
    #pragma unroll 8
    for (int k = 0; k < 64; k++) {
        f += st[r * 64 + k] * fw[k * 64 + d];
        f += sao[r * 64 + k] * fw[(64 + k) * 64 + d];
    }
    float y = f + st[r * 64 + d];
    __syncthreads();
    sy[r * 64 + d] = y;
    __syncthreads();
    float mu = 0.f;
    #pragma unroll 16
    for (int k = 0; k < 64; k++) mu += sy[r * 64 + k];
    mu *= (1.0f / 64.0f);
    float var = 0.f;
    #pragma unroll 16
    for (int k = 0; k < 64; k++) { float tt = sy[r * 64 + k] - mu; var += tt * tt; }
    var *= (1.0f / 64.0f);
    out[(size_t)row * 64 + d] = (y - mu) * rsqrtf(var + 1e-5f) * ln_g[d] + ln_b[d];
}

extern "C" void kernel_launch(void* const* d_in, const int* in_sizes, int n_in,
                              void* d_out, int out_size) {
    const float* graph     = (const float*)d_in[0];
    const float* drug_f    = (const float*)d_in[1];
    const float* disease_f = (const float*)d_in[2];
    const int*   tsteps    = (const int*)  d_in[3];
    const float* drug_w    = (const float*)d_in[4];
    const float* disease_w = (const float*)d_in[5];
    const float* emb_w     = (const float*)d_in[6];
    const float* emb_b     = (const float*)d_in[7];
    const float* in_w      = (const float*)d_in[8];
    const float* in_b      = (const float*)d_in[9];
    const float* out_w     = (const float*)d_in[10];
    const float* out_b     = (const float*)d_in[11];
    const float* wq = (const float*)d_in[12]; const float* bq = (const float*)d_in[13];
    const float* wk = (const float*)d_in[14]; const float* bk = (const float*)d_in[15];
    const float* wv = (const float*)d_in[16]; const float* bv = (const float*)d_in[17];
    const float* wo = (const float*)d_in[18]; const float* bo = (const float*)d_in[19];
    const float* fuse_w = (const float*)d_in[20]; const float* fuse_b = (const float*)d_in[21];
    const float* ln_g   = (const float*)d_in[22]; const float* ln_b   = (const float*)d_in[23];
    float* out = (float*)d_out;

    static int attr_set = 0;
    if (!attr_set) {
        cudaFuncSetAttribute(k_qkv,   cudaFuncAttributeMaxDynamicSharedMemorySize, 121856);
        cudaFuncSetAttribute(k_final, cudaFuncAttributeMaxDynamicSharedMemorySize, 49152);
        attr_set = 1;
    }

    k_degproj<<<768, 256>>>(graph, drug_f, disease_f, drug_w, disease_w);
    k_spmm   <<<dim3(48, 3), 256>>>(graph);
    k_mlp    <<<768, 256>>>(tsteps, emb_w, emb_b, in_w, in_b, out_w, out_b);
    k_qkv    <<<48, 256, 121856>>>(wq, bq, wk, bk, wv, bv);
    k_attn   <<<dim3(24, 4, 3), 256>>>();
    k_final  <<<1536, 256, 49152>>>(wo, bo, fuse_w, fuse_b, ln_g, ln_b, out);
}

// round 15
// speedup vs baseline: 1.2213x; 1.1516x over previous
#include <cuda_runtime.h>
#include <cuda_fp16.h>
#include <math.h>

#define NN 6144
#define NDRUG 3072

// ---------- scratch (device globals; no allocation allowed) ----------
__device__ __align__(16) float g_norm[NN];
__device__ __align__(16) float g_xn[NN * 64];
__device__ __align__(16) float g_target[NN * 64];
__device__ __align__(16) float g_aux[NN * 64];
__device__ __align__(16) float g_q[4 * NN * 16];    // head-major
__device__ __align__(16) float g_k[4 * NN * 16];
__device__ __align__(16) float g_v[4 * NN * 16];
__device__ __align__(16) float g_oacc[NN * 64];
__device__ __align__(16) float g_lacc[NN * 4];

#define MMA_TF32(D, A, B0, B1) \
    asm volatile("mma.sync.aligned.m16n8k8.row.col.f32.tf32.tf32.f32 " \
                 "{%0,%1,%2,%3},{%4,%5,%6,%7},{%8,%9},{%0,%1,%2,%3};" \
                 : "+f"((D)[0]), "+f"((D)[1]), "+f"((D)[2]), "+f"((D)[3]) \
                 : "r"((A)[0]), "r"((A)[1]), "r"((A)[2]), "r"((A)[3]), "r"(B0), "r"(B1))

#define MMA_F16(D, A, B0, B1) \
    asm volatile("mma.sync.aligned.m16n8k16.row.col.f32.f16.f16.f32 " \
                 "{%0,%1,%2,%3},{%4,%5,%6,%7},{%8,%9},{%0,%1,%2,%3};" \
                 : "+f"((D)[0]), "+f"((D)[1]), "+f"((D)[2]), "+f"((D)[3]) \
                 : "r"((A)[0]), "r"((A)[1]), "r"((A)[2]), "r"((A)[3]), "r"(B0), "r"(B1))

__device__ __forceinline__ unsigned h2u(float a, float b) {
    __half2 h = __floats2half2_rn(a, b);
    return *reinterpret_cast<unsigned*>(&h);
}

// ===== K1: degree norms + per-type projection + zero accumulators. grid 768, block 256 =====
__global__ __launch_bounds__(256) void k_degproj(const float* __restrict__ graph,
                                                 const float* __restrict__ drug_f,
                                                 const float* __restrict__ dis_f,
                                                 const float* __restrict__ drug_w,
                                                 const float* __restrict__ dis_w) {
    __shared__ float w[4096];
    __shared__ float fr[512];
    __shared__ float nrm[8];
    int tid = threadIdx.x;
    int wid = tid >> 5, lane = tid & 31;
    int row0 = blockIdx.x * 8;
    int row = row0 + wid;
    const float4* gr = reinterpret_cast<const float4*>(graph + (size_t)row * NN);
    float s = 0.f;
    #pragma unroll 4
    for (int i = lane; i < NN / 4; i += 32) { float4 t = gr[i]; s += (t.x + t.y) + (t.z + t.w); }
    #pragma unroll
    for (int o = 16; o; o >>= 1) s += __shfl_xor_sync(0xffffffffu, s, o);
    if (lane == 0) { float nr = rsqrtf(fmaxf(s, 1.0f)); g_norm[row] = nr; nrm[wid] = nr; }
    int t0 = blockIdx.x * 256 + tid;
    g_target[t0] = 0.f; g_target[t0 + 196608] = 0.f;
    g_oacc[t0] = 0.f;   g_oacc[t0 + 196608] = 0.f;
    if (t0 < NN * 4) g_lacc[t0] = 0.f;
    const float* W = (row0 < NDRUG) ? drug_w : dis_w;
    for (int i = tid; i < 4096; i += 256) w[i] = W[i];
    for (int rep = 0; rep < 2; rep++) {
        int idx = rep * 256 + tid;
        int r = idx >> 6, d = idx & 63;
        int rr = row0 + r;
        fr[idx] = (row0 < NDRUG) ? drug_f[(size_t)rr * 64 + d]
                                 : dis_f[(size_t)(rr - NDRUG) * 64 + d];
    }
    __syncthreads();
    for (int rep = 0; rep < 2; rep++) {
        int idx = rep * 256 + tid;
        int r = idx >> 6, d = idx & 63;
        float acc = 0.f;
        #pragma unroll 16
        for (int k = 0; k < 64; k++) acc += fr[r * 64 + k] * w[k * 64 + d];
        g_xn[(size_t)(row0 + r) * 64 + d] = acc * nrm[r];
    }
}

// ===== K2: target += (graph @ xn) * row_norm via tf32 mma. grid (48,3), block 256 =====
#define AST 36
#define BST 72
__global__ __launch_bounds__(256) void k_spmm(const float* __restrict__ graph) {
    __shared__ __align__(16) float As[128 * AST];
    __shared__ __align__(16) float Bs[32 * BST];
    int tid = threadIdx.x;
    int w = tid >> 5, lane = tid & 31, g = lane >> 2, t = lane & 3;
    int rowbase = blockIdx.x * 128;
    int kstart = blockIdx.y * 2048;

    float o[8][4];
    #pragma unroll
    for (int nt = 0; nt < 8; nt++)
        #pragma unroll
        for (int i = 0; i < 4; i++) o[nt][i] = 0.f;

    int ar = tid >> 1, ac = (tid & 1) * 16;
    int br = tid >> 3, bc = (tid & 7) * 8;

    for (int kb = 0; kb < 2048; kb += 32) {
        const float* gp = graph + (size_t)(rowbase + ar) * NN + kstart + kb + ac;
        float4 a0 = *reinterpret_cast<const float4*>(gp);
        float4 a1 = *reinterpret_cast<const float4*>(gp + 4);
        float4 a2 = *reinterpret_cast<const float4*>(gp + 8);
        float4 a3 = *reinterpret_cast<const float4*>(gp + 12);
        const float* bp = g_xn + (size_t)(kstart + kb + br) * 64 + bc;
        float4 b0 = *reinterpret_cast<const float4*>(bp);
        float4 b1 = *reinterpret_cast<const float4*>(bp + 4);
        __syncthreads();
        *reinterpret_cast<float4*>(As + ar * AST + ac)      = a0;
        *reinterpret_cast<float4*>(As + ar * AST + ac + 4)  = a1;
        *reinterpret_cast<float4*>(As + ar * AST + ac + 8)  = a2;
        *reinterpret_cast<float4*>(As + ar * AST + ac + 12) = a3;
        *reinterpret_cast<float4*>(Bs + br * BST + bc)     = b0;
        *reinterpret_cast<float4*>(Bs + br * BST + bc + 4) = b1;
        __syncthreads();
        #pragma unroll
        for (int kc = 0; kc < 4; kc++) {
            unsigned a[4];
            a[0] = __float_as_uint(As[(w * 16 + g) * AST + kc * 8 + t]);
            a[1] = __float_as_uint(As[(w * 16 + g + 8) * AST + kc * 8 + t]);
            a[2] = __float_as_uint(As[(w * 16 + g) * AST + kc * 8 + t + 4]);
            a[3] = __float_as_uint(As[(w * 16 + g + 8) * AST + kc * 8 + t + 4]);
            #pragma unroll
            for (int nt = 0; nt < 8; nt++) {
                unsigned bb0 = __float_as_uint(Bs[(kc * 8 + t) * BST + nt * 8 + g]);
                unsigned bb1 = __float_as_uint(Bs[(kc * 8 + t + 4) * BST + nt * 8 + g]);
                MMA_TF32(o[nt], a, bb0, bb1);
            }
        }
    }
    int r0 = rowbase + w * 16 + g, r1 = r0 + 8;
    float n0 = g_norm[r0], n1 = g_norm[r1];
    #pragma unroll
    for (int nt = 0; nt < 8; nt++) {
        int c = nt * 8 + 2 * t;
        atomicAdd(&g_target[(size_t)r0 * 64 + c],     o[nt][0] * n0);
        atomicAdd(&g_target[(size_t)r0 * 64 + c + 1], o[nt][1] * n0);
        atomicAdd(&g_target[(size_t)r1 * 64 + c],     o[nt][2] * n1);
        atomicAdd(&g_target[(size_t)r1 * 64 + c + 1], o[nt][3] * n1);
    }
}

// ===== K3: time embedding + MLP -> aux. grid 768, block 256, 8 nodes/CTA =====
__global__ __launch_bounds__(256) void k_mlp(const int* __restrict__ tsteps,
                                             const float* __restrict__ emb_w, const float* __restrict__ emb_b,
                                             const float* __restrict__ in_w,  const float* __restrict__ in_b,
                                             const float* __restrict__ out_w, const float* __restrict__ out_b) {
    __shared__ float cs[8 * 81];
    __shared__ float hs[8 * 257];
    int tid = threadIdx.x;
    int base = blockIdx.x * 8;
    for (int idx = tid; idx < 8 * 64; idx += 256) {
        int n = idx >> 6, d = idx & 63;
        cs[n * 81 + d] = g_target[(size_t)(base + n) * 64 + d];
    }
    if (tid < 128) {
        int n = tid >> 4, e = tid & 15;
        float t = (float)tsteps[base + n];
        float acc = emb_b[e];
        for (int k = 0; k < 16; k++) {
            int j = k & 7;
            float fr = expf(-1.15129254649702f * (float)j);
            float te = (k < 8) ? cosf(t * fr) : sinf(t * fr);
            acc += te * emb_w[k * 16 + e];
        }
        cs[n * 81 + 64 + e] = acc;
    }
    __syncthreads();
    {
        float acc[8];
        #pragma unroll
        for (int n = 0; n < 8; n++) acc[n] = 0.f;
        #pragma unroll 4
        for (int k = 0; k < 80; k++) {
            float w = in_w[k * 256 + tid];
            #pragma unroll
            for (int n = 0; n < 8; n++) acc[n] += cs[n * 81 + k] * w;
        }
        float bj = in_b[tid];
        #pragma unroll
        for (int n = 0; n < 8; n++) hs[n * 257 + tid] = tanhf(acc[n] + bj);
    }
    __syncthreads();
    {
        int d = tid & 63, gg = tid >> 6;
        float oa0 = 0.f, oa1 = 0.f;
        #pragma unroll 4
        for (int k = 0; k < 256; k++) {
            float w = out_w[k * 64 + d];
            oa0 += hs[(gg * 2 + 0) * 257 + k] * w;
            oa1 += hs[(gg * 2 + 1) * 257 + k] * w;
        }
        float bd = out_b[d];
        g_aux[(size_t)(base + gg * 2 + 0) * 64 + d] = oa0 + bd;
        g_aux[(size_t)(base + gg * 2 + 1) * 64 + d] = oa1 + bd;
    }
}

// ===== K4: fused q/k/v projections via tf32 mma. grid 48, block 256, dyn smem 121856 B =====
#define QST 68
__global__ __launch_bounds__(256) void k_qkv(const float* __restrict__ wq, const float* __restrict__ bq,
                                             const float* __restrict__ wk, const float* __restrict__ bk,
                                             const float* __restrict__ wv, const float* __restrict__ bv) {
    extern __shared__ float qs[];
    float* At = qs;                   // 128*68
    float* Aa = qs + 128 * QST;       // 128*68
    float* Ws = qs + 256 * QST;       // 192*68 (transposed weights)
    __shared__ float bias[192];
    int tid = threadIdx.x;
    int w = tid >> 5, lane = tid & 31, g = lane >> 2, t = lane & 3;
    int row0 = blockIdx.x * 128;

    for (int i = tid; i < 128 * 16; i += 256) {
        int r = i >> 4, c4 = (i & 15) * 4;
        float4 tv = *reinterpret_cast<const float4*>(g_target + (size_t)(row0 + r) * 64 + c4);
        float4 av = *reinterpret_cast<const float4*>(g_aux + (size_t)(row0 + r) * 64 + c4);
        float* td = At + r * QST + c4;
        td[0] = tv.x; td[1] = tv.y; td[2] = tv.z; td[3] = tv.w;
        float* ad = Aa + r * QST + c4;
        ad[0] = av.x; ad[1] = av.y; ad[2] = av.z; ad[3] = av.w;
    }
    for (int i = tid; i < 4096; i += 256) {
        int k = i >> 6, d = i & 63;
        Ws[d * QST + k]         = wq[i];
        Ws[(64 + d) * QST + k]  = wk[i];
        Ws[(128 + d) * QST + k] = wv[i];
    }
    if (tid < 192) bias[tid] = (tid < 64) ? bq[tid] : (tid < 128) ? bk[tid - 64] : bv[tid - 128];
    __syncthreads();

    float acc[24][4];
    #pragma unroll
    for (int nt = 0; nt < 24; nt++)
        #pragma unroll
        for (int i = 0; i < 4; i++) acc[nt][i] = 0.f;

    #pragma unroll
    for (int kc = 0; kc < 8; kc++) {
        unsigned at[4], aa[4];
        at[0] = __float_as_uint(At[(w * 16 + g) * QST + kc * 8 + t]);
        at[1] = __float_as_uint(At[(w * 16 + g + 8) * QST + kc * 8 + t]);
        at[2] = __float_as_uint(At[(w * 16 + g) * QST + kc * 8 + t + 4]);
        at[3] = __float_as_uint(At[(w * 16 + g + 8) * QST + kc * 8 + t + 4]);
        aa[0] = __float_as_uint(Aa[(w * 16 + g) * QST + kc * 8 + t]);
        aa[1] = __float_as_uint(Aa[(w * 16 + g + 8) * QST + kc * 8 + t]);
        aa[2] = __float_as_uint(Aa[(w * 16 + g) * QST + kc * 8 + t + 4]);
        aa[3] = __float_as_uint(Aa[(w * 16 + g + 8) * QST + kc * 8 + t + 4]);
        #pragma unroll
        for (int nt = 0; nt < 24; nt++) {
            unsigned b0 = __float_as_uint(Ws[(nt * 8 + g) * QST + kc * 8 + t]);
            unsigned b1 = __float_as_uint(Ws[(nt * 8 + g) * QST + kc * 8 + t + 4]);
            MMA_TF32(acc[nt], (nt < 8) ? at : aa, b0, b1);
        }
    }

    int r0 = row0 + w * 16 + g, r1 = r0 + 8;
    #pragma unroll
    for (int nt = 0; nt < 24; nt++) {
        int jj = nt * 8 + 2 * t;
        int sel = jj >> 6, jl = jj & 63;
        float* D = (sel == 0) ? g_q : (sel == 1) ? g_k : g_v;
        int h = jl >> 4, hd = jl & 15;
        int h2 = (jl + 1) >> 4, hd2 = (jl + 1) & 15;
        float b0 = bias[jj], b1 = bias[jj + 1];
        D[((size_t)h * NN + r0) * 16 + hd]   = acc[nt][0] + b0;
        D[((size_t)h2 * NN + r0) * 16 + hd2] = acc[nt][1] + b1;
        D[((size_t)h * NN + r1) * 16 + hd]   = acc[nt][2] + b0;
        D[((size_t)h2 * NN + r1) * 16 + hd2] = acc[nt][3] + b1;
    }
}

// ===== K5: attention via fp16 m16n8k16 mma. grid (24,4,6), block 256 =====
#define KST 20   // halves per key row (16 + pad)
#define VTS 72   // halves per dim row (64 keys + pad)
__global__ __launch_bounds__(256) void k_attn() {
    __shared__ __half Ks[64 * KST];    // K block [key][dim] fp16
    __shared__ __half Vt[16 * VTS];    // V block transposed [dim][key] fp16
    int tid = threadIdx.x;
    int w = tid >> 5, lane = tid & 31;
    int g = lane >> 2, t = lane & 3;
    int h = blockIdx.y;
    int qn0 = blockIdx.x * 256 + w * 32;

    // Q fragments fp16 (scale 0.25 folded)
    const float* qb = g_q + ((size_t)h * NN + qn0) * 16;
    unsigned aq[2][4];
    #pragma unroll
    for (int mt = 0; mt < 2; mt++) {
        const float* r0p = qb + (mt * 16 + g) * 16;
        const float* r1p = qb + (mt * 16 + g + 8) * 16;
        aq[mt][0] = h2u(0.25f * r0p[2 * t],     0.25f * r0p[2 * t + 1]);
        aq[mt][1] = h2u(0.25f * r1p[2 * t],     0.25f * r1p[2 * t + 1]);
        aq[mt][2] = h2u(0.25f * r0p[2 * t + 8], 0.25f * r0p[2 * t + 9]);
        aq[mt][3] = h2u(0.25f * r1p[2 * t + 8], 0.25f * r1p[2 * t + 9]);
    }

    float o[2][2][4];
    #pragma unroll
    for (int mt = 0; mt < 2; mt++)
        #pragma unroll
        for (int vt = 0; vt < 2; vt++)
            #pragma unroll
            for (int i = 0; i < 4; i++) o[mt][vt][i] = 0.f;
    float ls[2][2] = {{0.f, 0.f}, {0.f, 0.f}};

    int kbase = blockIdx.z * 1024;
    int krow = tid >> 2, kq = tid & 3;

    float4 kv = *reinterpret_cast<const float4*>(g_k + ((size_t)h * NN + kbase + krow) * 16 + kq * 4);
    float4 vv = *reinterpret_cast<const float4*>(g_v + ((size_t)h * NN + kbase + krow) * 16 + kq * 4);

    for (int c0 = 0; c0 < 1024; c0 += 64) {
        __syncthreads();
        {
            __half2* kd = reinterpret_cast<__half2*>(Ks + krow * KST + kq * 4);
            kd[0] = __floats2half2_rn(kv.x, kv.y);
            kd[1] = __floats2half2_rn(kv.z, kv.w);
            Vt[(kq * 4 + 0) * VTS + krow] = __float2half_rn(vv.x);
            Vt[(kq * 4 + 1) * VTS + krow] = __float2half_rn(vv.y);
            Vt[(kq * 4 + 2) * VTS + krow] = __float2half_rn(vv.z);
            Vt[(kq * 4 + 3) * VTS + krow] = __float2half_rn(vv.w);
        }
        __syncthreads();
        if (c0 + 64 < 1024) {
            int key = kbase + c0 + 64 + krow;
            kv = *reinterpret_cast<const float4*>(g_k + ((size_t)h * NN + key) * 16 + kq * 4);
            vv = *reinterpret_cast<const float4*>(g_v + ((size_t)h * NN + key) * 16 + kq * 4);
        }

        #pragma unroll
        for (int kc = 0; kc < 4; kc++) {   // 16-key chunks
            float d[2][2][4];
            #pragma unroll
            for (int mt = 0; mt < 2; mt++)
                #pragma unroll
                for (int sub = 0; sub < 2; sub++)
                    #pragma unroll
                    for (int i = 0; i < 4; i++) d[mt][sub][i] = 0.f;
            #pragma unroll
            for (int sub = 0; sub < 2; sub++) {
                int nt = kc * 2 + sub;
                unsigned b0 = *reinterpret_cast<unsigned*>(Ks + (nt * 8 + g) * KST + 2 * t);
                unsigned b1 = *reinterpret_cast<unsigned*>(Ks + (nt * 8 + g) * KST + 2 * t + 8);
                MMA_F16(d[0][sub], aq[0], b0, b1);
                MMA_F16(d[1][sub], aq[1], b0, b1);
            }
            // exp + denominators
            #pragma unroll
            for (int mt = 0; mt < 2; mt++)
                #pragma unroll
                for (int sub = 0; sub < 2; sub++) {
                    #pragma unroll
                    for (int i = 0; i < 4; i++) d[mt][sub][i] = __expf(d[mt][sub][i]);
                    ls[mt][0] += d[mt][sub][0] + d[mt][sub][1];
                    ls[mt][1] += d[mt][sub][2] + d[mt][sub][3];
                }
            // P C-frags -> fp16 A-frags (no shuffles)
            unsigned pa[2][4];
            #pragma unroll
            for (int mt = 0; mt < 2; mt++) {
                pa[mt][0] = h2u(d[mt][0][0], d[mt][0][1]);
                pa[mt][1] = h2u(d[mt][0][2], d[mt][0][3]);
                pa[mt][2] = h2u(d[mt][1][0], d[mt][1][1]);
                pa[mt][3] = h2u(d[mt][1][2], d[mt][1][3]);
            }
            // O += P V
            #pragma unroll
            for (int vt = 0; vt < 2; vt++) {
                unsigned b0 = *reinterpret_cast<unsigned*>(Vt + (vt * 8 + g) * VTS + kc * 16 + 2 * t);
                unsigned b1 = *reinterpret_cast<unsigned*>(Vt + (vt * 8 + g) * VTS + kc * 16 + 2 * t + 8);
                MMA_F16(o[0][vt], pa[0], b0, b1);
                MMA_F16(o[1][vt], pa[1], b0, b1);
            }
        }
    }

    #pragma unroll
    for (int mt = 0; mt < 2; mt++)
        #pragma unroll
        for (int i = 0; i < 2; i++) {
            ls[mt][i] += __shfl_xor_sync(0xffffffffu, ls[mt][i], 1);
            ls[mt][i] += __shfl_xor_sync(0xffffffffu, ls[mt][i], 2);
        }

    #pragma unroll
    for (int mt = 0; mt < 2; mt++) {
        int r0 = qn0 + mt * 16 + g, r1 = r0 + 8;
        #pragma unroll
        for (int vt = 0; vt < 2; vt++) {
            int c = h * 16 + vt * 8 + 2 * t;
            atomicAdd(&g_oacc[(size_t)r0 * 64 + c],     o[mt][vt][0]);
            atomicAdd(&g_oacc[(size_t)r0 * 64 + c + 1], o[mt][vt][1]);
            atomicAdd(&g_oacc[(size_t)r1 * 64 + c],     o[mt][vt][2]);
            atomicAdd(&g_oacc[(size_t)r1 * 64 + c + 1], o[mt][vt][3]);
        }
        if (t == 0) {
            atomicAdd(&g_lacc[r0 * 4 + h], ls[mt][0]);
            atomicAdd(&g_lacc[r1 * 4 + h], ls[mt][1]);
        }
    }
}

// ===== K6: wo proj + fuse + residual LN -> out. grid 1536, block 256, dyn smem 49152 =====
__global__ __launch_bounds__(256) void k_final(const float* __restrict__ wo, const float* __restrict__ bo,
                                               const float* __restrict__ fuse_w, const float* __restrict__ fuse_b,
                                               const float* __restrict__ ln_g, const float* __restrict__ ln_b,
                                               float* __restrict__ out) {
    extern __shared__ float fsm[];
    float* wo_s = fsm;          // 4096
    float* fw   = fsm + 4096;   // 8192
    __shared__ float st[256], sao[256], sy[256];
    int r = threadIdx.x >> 6, d = threadIdx.x & 63;
    int row = blockIdx.x * 4 + r;
    for (int i = threadIdx.x; i < 4096 / 4; i += 256)
        reinterpret_cast<float4*>(wo_s)[i] = reinterpret_cast<const float4*>(wo)[i];
    for (int i = threadIdx.x; i < 8192 / 4; i += 256)
        reinterpret_cast<float4*>(fw)[i] = reinterpret_cast<const float4*>(fuse_w)[i];
    st[r * 64 + d] = g_target[(size_t)row * 64 + d];
    float lh = g_lacc[row * 4 + (d >> 4)];
    sy[r * 64 + d] = g_oacc[(size_t)row * 64 + d] / lh;
    __syncthreads();
    float acc = bo[d];
    #pragma unroll 16
    for (int k = 0; k < 64; k++) acc += sy[r * 64 + k] * wo_s[k * 64 + d];
    sao[r * 64 + d] = acc;
    __syncthreads();
    float f = fuse_b[d];
    #pragma unroll 8
    for (int k = 0; k < 64; k++) {
        f += st[r * 64 + k] * fw[k * 64 + d];
        f += sao[r * 64 + k] * fw[(64 + k) * 64 + d];
    }
    float y = f + st[r * 64 + d];
    __syncthreads();
    sy[r * 64 + d] = y;
    __syncthreads();
    float mu = 0.f;
    #pragma unroll 16
    for (int k = 0; k < 64; k++) mu += sy[r * 64 + k];
    mu *= (1.0f / 64.0f);
    float var = 0.f;
    #pragma unroll 16
    for (int k = 0; k < 64; k++) { float tt = sy[r * 64 + k] - mu; var += tt * tt; }
    var *= (1.0f / 64.0f);
    out[(size_t)row * 64 + d] = (y - mu) * rsqrtf(var + 1e-5f) * ln_g[d] + ln_b[d];
}

extern "C" void kernel_launch(void* const* d_in, const int* in_sizes, int n_in,
                              void* d_out, int out_size) {
    const float* graph     = (const float*)d_in[0];
    const float* drug_f    = (const float*)d_in[1];
    const float* disease_f = (const float*)d_in[2];
    const int*   tsteps    = (const int*)  d_in[3];
    const float* drug_w    = (const float*)d_in[4];
    const float* disease_w = (const float*)d_in[5];
    const float* emb_w     = (const float*)d_in[6];
    const float* emb_b     = (const float*)d_in[7];
    const float* in_w      = (const float*)d_in[8];
    const float* in_b      = (const float*)d_in[9];
    const float* out_w     = (const float*)d_in[10];
    const float* out_b     = (const float*)d_in[11];
    const float* wq = (const float*)d_in[12]; const float* bq = (const float*)d_in[13];
    const float* wk = (const float*)d_in[14]; const float* bk = (const float*)d_in[15];
    const float* wv = (const float*)d_in[16]; const float* bv = (const float*)d_in[17];
    const float* wo = (const float*)d_in[18]; const float* bo = (const float*)d_in[19];
    const float* fuse_w = (const float*)d_in[20]; const float* fuse_b = (const float*)d_in[21];
    const float* ln_g   = (const float*)d_in[22]; const float* ln_b   = (const float*)d_in[23];
    float* out = (float*)d_out;

    static int attr_set = 0;
    if (!attr_set) {
        cudaFuncSetAttribute(k_qkv,   cudaFuncAttributeMaxDynamicSharedMemorySize, 121856);
        cudaFuncSetAttribute(k_final, cudaFuncAttributeMaxDynamicSharedMemorySize, 49152);
        attr_set = 1;
    }

    k_degproj<<<768, 256>>>(graph, drug_f, disease_f, drug_w, disease_w);
    k_spmm   <<<dim3(48, 3), 256>>>(graph);
    k_mlp    <<<768, 256>>>(tsteps, emb_w, emb_b, in_w, in_b, out_w, out_b);
    k_qkv    <<<48, 256, 121856>>>(wq, bq, wk, bk, wv, bv);
    k_attn   <<<dim3(24, 4, 6), 256>>>();
    k_final  <<<1536, 256, 49152>>>(wo, bo, fuse_w, fuse_b, ln_g, ln_b, out);
}

// round 16
// speedup vs baseline: 1.2873x; 1.0540x over previous
#include <cuda_runtime.h>
#include <cuda_fp16.h>
#include <math.h>

#define NN 6144
#define NDRUG 3072

// ---------- scratch (device globals; no allocation allowed) ----------
__device__ __align__(16) float g_norm[NN];
__device__ __align__(16) float g_xn[NN * 64];
__device__ __align__(16) float g_target[NN * 64];
__device__ __align__(16) float g_aux[NN * 64];
__device__ __align__(16) float g_q[4 * NN * 16];    // head-major
__device__ __align__(16) float g_k[4 * NN * 16];
__device__ __align__(16) float g_v[4 * NN * 16];
__device__ __align__(16) float g_oacc[NN * 64];
__device__ __align__(16) float g_lacc[NN * 4];

#define MMA_TF32(D, A, B0, B1) \
    asm volatile("mma.sync.aligned.m16n8k8.row.col.f32.tf32.tf32.f32 " \
                 "{%0,%1,%2,%3},{%4,%5,%6,%7},{%8,%9},{%0,%1,%2,%3};" \
                 : "+f"((D)[0]), "+f"((D)[1]), "+f"((D)[2]), "+f"((D)[3]) \
                 : "r"((A)[0]), "r"((A)[1]), "r"((A)[2]), "r"((A)[3]), "r"(B0), "r"(B1))

#define MMA_F16(D, A, B0, B1) \
    asm volatile("mma.sync.aligned.m16n8k16.row.col.f32.f16.f16.f32 " \
                 "{%0,%1,%2,%3},{%4,%5,%6,%7},{%8,%9},{%0,%1,%2,%3};" \
                 : "+f"((D)[0]), "+f"((D)[1]), "+f"((D)[2]), "+f"((D)[3]) \
                 : "r"((A)[0]), "r"((A)[1]), "r"((A)[2]), "r"((A)[3]), "r"(B0), "r"(B1))

__device__ __forceinline__ unsigned h2u(float a, float b) {
    __half2 h = __floats2half2_rn(a, b);
    return *reinterpret_cast<unsigned*>(&h);
}

// ===== K1: degree norms + per-type projection + zero accumulators. grid 768, block 256 =====
__global__ __launch_bounds__(256) void k_degproj(const float* __restrict__ graph,
                                                 const float* __restrict__ drug_f,
                                                 const float* __restrict__ dis_f,
                                                 const float* __restrict__ drug_w,
                                                 const float* __restrict__ dis_w) {
    __shared__ float w[4096];
    __shared__ float fr[512];
    __shared__ float nrm[8];
    int tid = threadIdx.x;
    int wid = tid >> 5, lane = tid & 31;
    int row0 = blockIdx.x * 8;
    int row = row0 + wid;
    const float4* gr = reinterpret_cast<const float4*>(graph + (size_t)row * NN);
    float s = 0.f;
    #pragma unroll 4
    for (int i = lane; i < NN / 4; i += 32) { float4 t = gr[i]; s += (t.x + t.y) + (t.z + t.w); }
    #pragma unroll
    for (int o = 16; o; o >>= 1) s += __shfl_xor_sync(0xffffffffu, s, o);
    if (lane == 0) { float nr = rsqrtf(fmaxf(s, 1.0f)); g_norm[row] = nr; nrm[wid] = nr; }
    int t0 = blockIdx.x * 256 + tid;
    g_target[t0] = 0.f; g_target[t0 + 196608] = 0.f;
    g_oacc[t0] = 0.f;   g_oacc[t0 + 196608] = 0.f;
    if (t0 < NN * 4) g_lacc[t0] = 0.f;
    const float* W = (row0 < NDRUG) ? drug_w : dis_w;
    for (int i = tid; i < 4096; i += 256) w[i] = W[i];
    for (int rep = 0; rep < 2; rep++) {
        int idx = rep * 256 + tid;
        int r = idx >> 6, d = idx & 63;
        int rr = row0 + r;
        fr[idx] = (row0 < NDRUG) ? drug_f[(size_t)rr * 64 + d]
                                 : dis_f[(size_t)(rr - NDRUG) * 64 + d];
    }
    __syncthreads();
    for (int rep = 0; rep < 2; rep++) {
        int idx = rep * 256 + tid;
        int r = idx >> 6, d = idx & 63;
        float acc = 0.f;
        #pragma unroll 16
        for (int k = 0; k < 64; k++) acc += fr[r * 64 + k] * w[k * 64 + d];
        g_xn[(size_t)(row0 + r) * 64 + d] = acc * nrm[r];
    }
}

// ===== K2: target += (graph @ xn) * row_norm via fp16 mma. grid (48,3), block 256 =====
#define AST2 40
#define BST2 40
__global__ __launch_bounds__(256) void k_spmm(const float* __restrict__ graph) {
    __shared__ __align__(16) __half As[128 * AST2];   // [row][k] fp16
    __shared__ __align__(16) __half Bt[64 * BST2];    // [dim][k] fp16 (transposed)
    int tid = threadIdx.x;
    int w = tid >> 5, lane = tid & 31, g = lane >> 2, t = lane & 3;
    int rowbase = blockIdx.x * 128;
    int kstart = blockIdx.y * 2048;

    float o[8][4];
    #pragma unroll
    for (int nt = 0; nt < 8; nt++)
        #pragma unroll
        for (int i = 0; i < 4; i++) o[nt][i] = 0.f;

    int ar = tid >> 1, ac = (tid & 1) * 16;
    int br = tid >> 3, bc = (tid & 7) * 8;

    for (int kb = 0; kb < 2048; kb += 32) {
        const float* gp = graph + (size_t)(rowbase + ar) * NN + kstart + kb + ac;
        float4 a0 = *reinterpret_cast<const float4*>(gp);
        float4 a1 = *reinterpret_cast<const float4*>(gp + 4);
        float4 a2 = *reinterpret_cast<const float4*>(gp + 8);
        float4 a3 = *reinterpret_cast<const float4*>(gp + 12);
        const float* bp = g_xn + (size_t)(kstart + kb + br) * 64 + bc;
        float4 b0 = *reinterpret_cast<const float4*>(bp);
        float4 b1 = *reinterpret_cast<const float4*>(bp + 4);
        __syncthreads();
        {
            __half2* ad = reinterpret_cast<__half2*>(As + ar * AST2 + ac);
            ad[0] = __floats2half2_rn(a0.x, a0.y);
            ad[1] = __floats2half2_rn(a0.z, a0.w);
            ad[2] = __floats2half2_rn(a1.x, a1.y);
            ad[3] = __floats2half2_rn(a1.z, a1.w);
            ad[4] = __floats2half2_rn(a2.x, a2.y);
            ad[5] = __floats2half2_rn(a2.z, a2.w);
            ad[6] = __floats2half2_rn(a3.x, a3.y);
            ad[7] = __floats2half2_rn(a3.z, a3.w);
            Bt[(bc + 0) * BST2 + br] = __float2half_rn(b0.x);
            Bt[(bc + 1) * BST2 + br] = __float2half_rn(b0.y);
            Bt[(bc + 2) * BST2 + br] = __float2half_rn(b0.z);
            Bt[(bc + 3) * BST2 + br] = __float2half_rn(b0.w);
            Bt[(bc + 4) * BST2 + br] = __float2half_rn(b1.x);
            Bt[(bc + 5) * BST2 + br] = __float2half_rn(b1.y);
            Bt[(bc + 6) * BST2 + br] = __float2half_rn(b1.z);
            Bt[(bc + 7) * BST2 + br] = __float2half_rn(b1.w);
        }
        __syncthreads();
        #pragma unroll
        for (int kc = 0; kc < 2; kc++) {   // two 16-k chunks
            unsigned a[4];
            a[0] = *reinterpret_cast<unsigned*>(As + (w * 16 + g) * AST2 + kc * 16 + 2 * t);
            a[1] = *reinterpret_cast<unsigned*>(As + (w * 16 + g + 8) * AST2 + kc * 16 + 2 * t);
            a[2] = *reinterpret_cast<unsigned*>(As + (w * 16 + g) * AST2 + kc * 16 + 2 * t + 8);
            a[3] = *reinterpret_cast<unsigned*>(As + (w * 16 + g + 8) * AST2 + kc * 16 + 2 * t + 8);
            #pragma unroll
            for (int nt = 0; nt < 8; nt++) {
                unsigned bb0 = *reinterpret_cast<unsigned*>(Bt + (nt * 8 + g) * BST2 + kc * 16 + 2 * t);
                unsigned bb1 = *reinterpret_cast<unsigned*>(Bt + (nt * 8 + g) * BST2 + kc * 16 + 2 * t + 8);
                MMA_F16(o[nt], a, bb0, bb1);
            }
        }
    }
    int r0 = rowbase + w * 16 + g, r1 = r0 + 8;
    float n0 = g_norm[r0], n1 = g_norm[r1];
    #pragma unroll
    for (int nt = 0; nt < 8; nt++) {
        int c = nt * 8 + 2 * t;
        atomicAdd(&g_target[(size_t)r0 * 64 + c],     o[nt][0] * n0);
        atomicAdd(&g_target[(size_t)r0 * 64 + c + 1], o[nt][1] * n0);
        atomicAdd(&g_target[(size_t)r1 * 64 + c],     o[nt][2] * n1);
        atomicAdd(&g_target[(size_t)r1 * 64 + c + 1], o[nt][3] * n1);
    }
}

// ===== K3: time embedding + MLP -> aux. grid 768, block 256, 8 nodes/CTA =====
__global__ __launch_bounds__(256) void k_mlp(const int* __restrict__ tsteps,
                                             const float* __restrict__ emb_w, const float* __restrict__ emb_b,
                                             const float* __restrict__ in_w,  const float* __restrict__ in_b,
                                             const float* __restrict__ out_w, const float* __restrict__ out_b) {
    __shared__ float cs[8 * 81];
    __shared__ float hs[8 * 257];
    int tid = threadIdx.x;
    int base = blockIdx.x * 8;
    for (int idx = tid; idx < 8 * 64; idx += 256) {
        int n = idx >> 6, d = idx & 63;
        cs[n * 81 + d] = g_target[(size_t)(base + n) * 64 + d];
    }
    if (tid < 128) {
        int n = tid >> 4, e = tid & 15;
        float t = (float)tsteps[base + n];
        float acc = emb_b[e];
        for (int k = 0; k < 16; k++) {
            int j = k & 7;
            float fr = expf(-1.15129254649702f * (float)j);
            float te = (k < 8) ? cosf(t * fr) : sinf(t * fr);
            acc += te * emb_w[k * 16 + e];
        }
        cs[n * 81 + 64 + e] = acc;
    }
    __syncthreads();
    {
        float acc[8];
        #pragma unroll
        for (int n = 0; n < 8; n++) acc[n] = 0.f;
        #pragma unroll 4
        for (int k = 0; k < 80; k++) {
            float w = in_w[k * 256 + tid];
            #pragma unroll
            for (int n = 0; n < 8; n++) acc[n] += cs[n * 81 + k] * w;
        }
        float bj = in_b[tid];
        #pragma unroll
        for (int n = 0; n < 8; n++) hs[n * 257 + tid] = tanhf(acc[n] + bj);
    }
    __syncthreads();
    {
        int d = tid & 63, gg = tid >> 6;
        float oa0 = 0.f, oa1 = 0.f;
        #pragma unroll 4
        for (int k = 0; k < 256; k++) {
            float w = out_w[k * 64 + d];
            oa0 += hs[(gg * 2 + 0) * 257 + k] * w;
            oa1 += hs[(gg * 2 + 1) * 257 + k] * w;
        }
        float bd = out_b[d];
        g_aux[(size_t)(base + gg * 2 + 0) * 64 + d] = oa0 + bd;
        g_aux[(size_t)(base + gg * 2 + 1) * 64 + d] = oa1 + bd;
    }
}

// ===== K4: fused q/k/v projections via tf32 mma. grid 48, block 256, dyn smem 121856 B =====
#define QST 68
__global__ __launch_bounds__(256) void k_qkv(const float* __restrict__ wq, const float* __restrict__ bq,
                                             const float* __restrict__ wk, const float* __restrict__ bk,
                                             const float* __restrict__ wv, const float* __restrict__ bv) {
    extern __shared__ float qs[];
    float* At = qs;                   // 128*68
    float* Aa = qs + 128 * QST;       // 128*68
    float* Ws = qs + 256 * QST;       // 192*68 (transposed weights)
    __shared__ float bias[192];
    int tid = threadIdx.x;
    int w = tid >> 5, lane = tid & 31, g = lane >> 2, t = lane & 3;
    int row0 = blockIdx.x * 128;

    for (int i = tid; i < 128 * 16; i += 256) {
        int r = i >> 4, c4 = (i & 15) * 4;
        float4 tv = *reinterpret_cast<const float4*>(g_target + (size_t)(row0 + r) * 64 + c4);
        float4 av = *reinterpret_cast<const float4*>(g_aux + (size_t)(row0 + r) * 64 + c4);
        float* td = At + r * QST + c4;
        td[0] = tv.x; td[1] = tv.y; td[2] = tv.z; td[3] = tv.w;
        float* ad = Aa + r * QST + c4;
        ad[0] = av.x; ad[1] = av.y; ad[2] = av.z; ad[3] = av.w;
    }
    for (int i = tid; i < 4096; i += 256) {
        int k = i >> 6, d = i & 63;
        Ws[d * QST + k]         = wq[i];
        Ws[(64 + d) * QST + k]  = wk[i];
        Ws[(128 + d) * QST + k] = wv[i];
    }
    if (tid < 192) bias[tid] = (tid < 64) ? bq[tid] : (tid < 128) ? bk[tid - 64] : bv[tid - 128];
    __syncthreads();

    float acc[24][4];
    #pragma unroll
    for (int nt = 0; nt < 24; nt++)
        #pragma unroll
        for (int i = 0; i < 4; i++) acc[nt][i] = 0.f;

    #pragma unroll
    for (int kc = 0; kc < 8; kc++) {
        unsigned at[4], aa[4];
        at[0] = __float_as_uint(At[(w * 16 + g) * QST + kc * 8 + t]);
        at[1] = __float_as_uint(At[(w * 16 + g + 8) * QST + kc * 8 + t]);
        at[2] = __float_as_uint(At[(w * 16 + g) * QST + kc * 8 + t + 4]);
        at[3] = __float_as_uint(At[(w * 16 + g + 8) * QST + kc * 8 + t + 4]);
        aa[0] = __float_as_uint(Aa[(w * 16 + g) * QST + kc * 8 + t]);
        aa[1] = __float_as_uint(Aa[(w * 16 + g + 8) * QST + kc * 8 + t]);
        aa[2] = __float_as_uint(Aa[(w * 16 + g) * QST + kc * 8 + t + 4]);
        aa[3] = __float_as_uint(Aa[(w * 16 + g + 8) * QST + kc * 8 + t + 4]);
        #pragma unroll
        for (int nt = 0; nt < 24; nt++) {
            unsigned b0 = __float_as_uint(Ws[(nt * 8 + g) * QST + kc * 8 + t]);
            unsigned b1 = __float_as_uint(Ws[(nt * 8 + g) * QST + kc * 8 + t + 4]);
            MMA_TF32(acc[nt], (nt < 8) ? at : aa, b0, b1);
        }
    }

    int r0 = row0 + w * 16 + g, r1 = r0 + 8;
    #pragma unroll
    for (int nt = 0; nt < 24; nt++) {
        int jj = nt * 8 + 2 * t;
        int sel = jj >> 6, jl = jj & 63;
        float* D = (sel == 0) ? g_q : (sel == 1) ? g_k : g_v;
        int h = jl >> 4, hd = jl & 15;
        int h2 = (jl + 1) >> 4, hd2 = (jl + 1) & 15;
        float b0 = bias[jj], b1 = bias[jj + 1];
        D[((size_t)h * NN + r0) * 16 + hd]   = acc[nt][0] + b0;
        D[((size_t)h2 * NN + r0) * 16 + hd2] = acc[nt][1] + b1;
        D[((size_t)h * NN + r1) * 16 + hd]   = acc[nt][2] + b0;
        D[((size_t)h2 * NN + r1) * 16 + hd2] = acc[nt][3] + b1;
    }
}

// ===== K5: attention via fp16 mma + ex2.approx.f16x2. grid (24,4,6), block 256 =====
#define KST 20
#define VTS 72
#define QSCL 0.36067376022224085f   // 0.25 * log2(e)
__global__ __launch_bounds__(256) void k_attn() {
    __shared__ __half Ks[64 * KST];
    __shared__ __half Vt[16 * VTS];
    int tid = threadIdx.x;
    int w = tid >> 5, lane = tid & 31;
    int g = lane >> 2, t = lane & 3;
    int h = blockIdx.y;
    int qn0 = blockIdx.x * 256 + w * 32;

    const float* qb = g_q + ((size_t)h * NN + qn0) * 16;
    unsigned aq[2][4];
    #pragma unroll
    for (int mt = 0; mt < 2; mt++) {
        const float* r0p = qb + (mt * 16 + g) * 16;
        const float* r1p = qb + (mt * 16 + g + 8) * 16;
        aq[mt][0] = h2u(QSCL * r0p[2 * t],     QSCL * r0p[2 * t + 1]);
        aq[mt][1] = h2u(QSCL * r1p[2 * t],     QSCL * r1p[2 * t + 1]);
        aq[mt][2] = h2u(QSCL * r0p[2 * t + 8], QSCL * r0p[2 * t + 9]);
        aq[mt][3] = h2u(QSCL * r1p[2 * t + 8], QSCL * r1p[2 * t + 9]);
    }

    float o[2][2][4];
    #pragma unroll
    for (int mt = 0; mt < 2; mt++)
        #pragma unroll
        for (int vt = 0; vt < 2; vt++)
            #pragma unroll
            for (int i = 0; i < 4; i++) o[mt][vt][i] = 0.f;
    float ls[2][2] = {{0.f, 0.f}, {0.f, 0.f}};

    int kbase = blockIdx.z * 1024;
    int krow = tid >> 2, kq = tid & 3;

    float4 kv = *reinterpret_cast<const float4*>(g_k + ((size_t)h * NN + kbase + krow) * 16 + kq * 4);
    float4 vv = *reinterpret_cast<const float4*>(g_v + ((size_t)h * NN + kbase + krow) * 16 + kq * 4);

    for (int c0 = 0; c0 < 1024; c0 += 64) {
        __syncthreads();
        {
            __half2* kd = reinterpret_cast<__half2*>(Ks + krow * KST + kq * 4);
            kd[0] = __floats2half2_rn(kv.x, kv.y);
            kd[1] = __floats2half2_rn(kv.z, kv.w);
            Vt[(kq * 4 + 0) * VTS + krow] = __float2half_rn(vv.x);
            Vt[(kq * 4 + 1) * VTS + krow] = __float2half_rn(vv.y);
            Vt[(kq * 4 + 2) * VTS + krow] = __float2half_rn(vv.z);
            Vt[(kq * 4 + 3) * VTS + krow] = __float2half_rn(vv.w);
        }
        __syncthreads();
        if (c0 + 64 < 1024) {
            int key = kbase + c0 + 64 + krow;
            kv = *reinterpret_cast<const float4*>(g_k + ((size_t)h * NN + key) * 16 + kq * 4);
            vv = *reinterpret_cast<const float4*>(g_v + ((size_t)h * NN + key) * 16 + kq * 4);
        }

        #pragma unroll
        for (int kc = 0; kc < 4; kc++) {
            float d[2][2][4];
            #pragma unroll
            for (int mt = 0; mt < 2; mt++)
                #pragma unroll
                for (int sub = 0; sub < 2; sub++)
                    #pragma unroll
                    for (int i = 0; i < 4; i++) d[mt][sub][i] = 0.f;
            #pragma unroll
            for (int sub = 0; sub < 2; sub++) {
                int nt = kc * 2 + sub;
                unsigned b0 = *reinterpret_cast<unsigned*>(Ks + (nt * 8 + g) * KST + 2 * t);
                unsigned b1 = *reinterpret_cast<unsigned*>(Ks + (nt * 8 + g) * KST + 2 * t + 8);
                MMA_F16(d[0][sub], aq[0], b0, b1);
                MMA_F16(d[1][sub], aq[1], b0, b1);
            }
            // pack x = s*log2e pairs to half2, exp via ex2.approx.f16x2
            unsigned pa[2][4];
            #pragma unroll
            for (int mt = 0; mt < 2; mt++) {
                pa[mt][0] = h2u(d[mt][0][0], d[mt][0][1]);
                pa[mt][1] = h2u(d[mt][0][2], d[mt][0][3]);
                pa[mt][2] = h2u(d[mt][1][0], d[mt][1][1]);
                pa[mt][3] = h2u(d[mt][1][2], d[mt][1][3]);
                #pragma unroll
                for (int j = 0; j < 4; j++)
                    asm("ex2.approx.f16x2 %0, %0;" : "+r"(pa[mt][j]));
                // denominators: rows g (pa0+pa2), rows g+8 (pa1+pa3)
                __half2 s0 = __hadd2(*reinterpret_cast<__half2*>(&pa[mt][0]),
                                     *reinterpret_cast<__half2*>(&pa[mt][2]));
                __half2 s1 = __hadd2(*reinterpret_cast<__half2*>(&pa[mt][1]),
                                     *reinterpret_cast<__half2*>(&pa[mt][3]));
                float2 f0 = __half22float2(s0);
                float2 f1 = __half22float2(s1);
                ls[mt][0] += f0.x + f0.y;
                ls[mt][1] += f1.x + f1.y;
            }
            // O += P V
            #pragma unroll
            for (int vt = 0; vt < 2; vt++) {
                unsigned b0 = *reinterpret_cast<unsigned*>(Vt + (vt * 8 + g) * VTS + kc * 16 + 2 * t);
                unsigned b1 = *reinterpret_cast<unsigned*>(Vt + (vt * 8 + g) * VTS + kc * 16 + 2 * t + 8);
                MMA_F16(o[0][vt], pa[0], b0, b1);
                MMA_F16(o[1][vt], pa[1], b0, b1);
            }
        }
    }

    #pragma unroll
    for (int mt = 0; mt < 2; mt++)
        #pragma unroll
        for (int i = 0; i < 2; i++) {
            ls[mt][i] += __shfl_xor_sync(0xffffffffu, ls[mt][i], 1);
            ls[mt][i] += __shfl_xor_sync(0xffffffffu, ls[mt][i], 2);
        }

    #pragma unroll
    for (int mt = 0; mt < 2; mt++) {
        int r0 = qn0 + mt * 16 + g, r1 = r0 + 8;
        #pragma unroll
        for (int vt = 0; vt < 2; vt++) {
            int c = h * 16 + vt * 8 + 2 * t;
            atomicAdd(&g_oacc[(size_t)r0 * 64 + c],     o[mt][vt][0]);
            atomicAdd(&g_oacc[(size_t)r0 * 64 + c + 1], o[mt][vt][1]);
            atomicAdd(&g_oacc[(size_t)r1 * 64 + c],     o[mt][vt][2]);
            atomicAdd(&g_oacc[(size_t)r1 * 64 + c + 1], o[mt][vt][3]);
        }
        if (t == 0) {
            atomicAdd(&g_lacc[r0 * 4 + h], ls[mt][0]);
            atomicAdd(&g_lacc[r1 * 4 + h], ls[mt][1]);
        }
    }
}

// ===== K6: wo proj + fuse + residual LN -> out. grid 1536, block 256, dyn smem 49152 =====
__global__ __launch_bounds__(256) void k_final(const float* __restrict__ wo, const float* __restrict__ bo,
                                               const float* __restrict__ fuse_w, const float* __restrict__ fuse_b,
                                               const float* __restrict__ ln_g, const float* __restrict__ ln_b,
                                               float* __restrict__ out) {
    extern __shared__ float fsm[];
    float* wo_s = fsm;          // 4096
    float* fw   = fsm + 4096;   // 8192
    __shared__ float st[256], sao[256], sy[256];
    int r = threadIdx.x >> 6, d = threadIdx.x & 63;
    int row = blockIdx.x * 4 + r;
    for (int i = threadIdx.x; i < 4096 / 4; i += 256)
        reinterpret_cast<float4*>(wo_s)[i] = reinterpret_cast<const float4*>(wo)[i];
    for (int i = threadIdx.x; i < 8192 / 4; i += 256)
        reinterpret_cast<float4*>(fw)[i] = reinterpret_cast<const float4*>(fuse_w)[i];
    st[r * 64 + d] = g_target[(size_t)row * 64 + d];
    float lh = g_lacc[row * 4 + (d >> 4)];
    sy[r * 64 + d] = g_oacc[(size_t)row * 64 + d] / lh;
    __syncthreads();
    float acc = bo[d];
    #pragma unroll 16
    for (int k = 0; k < 64; k++) acc += sy[r * 64 + k] * wo_s[k * 64 + d];
    sao[r * 64 + d] = acc;
    __syncthreads();
    float f = fuse_b[d];
    #pragma unroll 8
    for (int k = 0; k < 64; k++) {
        f += st[r * 64 + k] * fw[k * 64 + d];
        f += sao[r * 64 + k] * fw[(64 + k) * 64 + d];
    }
    float y = f + st[r * 64 + d];
    __syncthreads();
    sy[r * 64 + d] = y;
    __syncthreads();
    float mu = 0.f;
    #pragma unroll 16
    for (int k = 0; k < 64; k++) mu += sy[r * 64 + k];
    mu *= (1.0f / 64.0f);
    float var = 0.f;
    #pragma unroll 16
    for (int k = 0; k < 64; k++) { float tt = sy[r * 64 + k] - mu; var += tt * tt; }
    var *= (1.0f / 64.0f);
    out[(size_t)row * 64 + d] = (y - mu) * rsqrtf(var + 1e-5f) * ln_g[d] + ln_b[d];
}

extern "C" void kernel_launch(void* const* d_in, const int* in_sizes, int n_in,
                              void* d_out, int out_size) {
    const float* graph     = (const float*)d_in[0];
    const float* drug_f    = (const float*)d_in[1];
    const float* disease_f = (const float*)d_in[2];
    const int*   tsteps    = (const int*)  d_in[3];
    const float* drug_w    = (const float*)d_in[4];
    const float* disease_w = (const float*)d_in[5];
    const float* emb_w     = (const float*)d_in[6];
    const float* emb_b     = (const float*)d_in[7];
    const float* in_w      = (const float*)d_in[8];
    const float* in_b      = (const float*)d_in[9];
    const float* out_w     = (const float*)d_in[10];
    const float* out_b     = (const float*)d_in[11];
    const float* wq = (const float*)d_in[12]; const float* bq = (const float*)d_in[13];
    const float* wk = (const float*)d_in[14]; const float* bk = (const float*)d_in[15];
    const float* wv = (const float*)d_in[16]; const float* bv = (const float*)d_in[17];
    const float* wo = (const float*)d_in[18]; const float* bo = (const float*)d_in[19];
    const float* fuse_w = (const float*)d_in[20]; const float* fuse_b = (const float*)d_in[21];
    const float* ln_g   = (const float*)d_in[22]; const float* ln_b   = (const float*)d_in[23];
    float* out = (float*)d_out;

    static int attr_set = 0;
    if (!attr_set) {
        cudaFuncSetAttribute(k_qkv,   cudaFuncAttributeMaxDynamicSharedMemorySize, 121856);
        cudaFuncSetAttribute(k_final, cudaFuncAttributeMaxDynamicSharedMemorySize, 49152);
        attr_set = 1;
    }

    k_degproj<<<768, 256>>>(graph, drug_f, disease_f, drug_w, disease_w);
    k_spmm   <<<dim3(48, 3), 256>>>(graph);
    k_mlp    <<<768, 256>>>(tsteps, emb_w, emb_b, in_w, in_b, out_w, out_b);
    k_qkv    <<<48, 256, 121856>>>(wq, bq, wk, bk, wv, bv);
    k_attn   <<<dim3(24, 4, 6), 256>>>();
    k_final  <<<1536, 256, 49152>>>(wo, bo, fuse_w, fuse_b, ln_g, ln_b, out);
}